// round 2
// baseline (speedup 1.0000x reference)
#include <cuda_runtime.h>
#include <cstdint>

#define Bb   16
#define Ll   1024
#define DM   384
#define DI   768
#define NS   16
#define DTR  24
#define DBCW 56            // DTR + 2*NS
#define BLr  16384         // Bb*Ll

// ---------------- scratch (device globals; no allocations) ----------------
__device__ float g_xn[BLr * (size_t)DM];              // 25 MB
__device__ float g_wt_in[(size_t)DM * 2 * DI];        // (384,1536)
__device__ float g_wt_out[(size_t)DI * DM];           // (768,384)
__device__ float g_xz[(size_t)BLr * 2 * DI];          // 100 MB
__device__ float g_xc[2][(size_t)BLr * DI];           // conv+silu output, per dir
__device__ float g_dbc[2][(size_t)BLr * DBCW];        // dt|B|C, per dir
__device__ float g_delta[2][(size_t)BLr * DI];        // softplus delta
__device__ float g_y[2][(size_t)BLr * DI];            // y*silu(z) at ORIGINAL positions

// ---------------- LayerNorm ----------------
__global__ __launch_bounds__(384) void ln_kernel(const float* __restrict__ x,
                                                 const float* __restrict__ w,
                                                 const float* __restrict__ b) {
    int r = blockIdx.x, t = threadIdx.x;
    float v = x[(size_t)r * DM + t];
    float s = v, s2 = v * v;
#pragma unroll
    for (int o = 16; o; o >>= 1) {
        s  += __shfl_xor_sync(0xffffffffu, s, o);
        s2 += __shfl_xor_sync(0xffffffffu, s2, o);
    }
    __shared__ float ps[12], ps2[12];
    __shared__ float smu, srstd;
    if ((t & 31) == 0) { ps[t >> 5] = s; ps2[t >> 5] = s2; }
    __syncthreads();
    if (t == 0) {
        float a = 0.f, a2 = 0.f;
#pragma unroll
        for (int i = 0; i < 12; i++) { a += ps[i]; a2 += ps2[i]; }
        float mu = a / DM;
        float var = a2 / DM - mu * mu;
        smu = mu; srstd = rsqrtf(var + 1e-5f);
    }
    __syncthreads();
    g_xn[(size_t)r * DM + t] = (v - smu) * srstd * w[t] + b[t];
}

// ---------------- weight transposes ----------------
__global__ void transpose_in(const float* __restrict__ W) {   // (1536,384)->(384,1536)
    int i = blockIdx.x * 256 + threadIdx.x;
    if (i < 1536 * 384) { int n = i / 384, k = i % 384; g_wt_in[(size_t)k * 1536 + n] = W[i]; }
}
__global__ void transpose_out(const float* __restrict__ W) {  // (384,768)->(768,384)
    int i = blockIdx.x * 256 + threadIdx.x;
    if (i < 384 * 768) { int n = i / 768, k = i % 768; g_wt_out[(size_t)k * 384 + n] = W[i]; }
}

// ---------------- SGEMM: xz = xn @ wt_in  (M=16384,N=1536,K=384) ----------------
__global__ __launch_bounds__(256) void sgemm_in() {
    const int BM = 128, BN = 128, BK = 8, TM = 8, TN = 8;
    const int N = 2 * DI, K = DM;
    __shared__ float As[BK * BM], Bs[BK * BN];
    int crow = blockIdx.y, ccol = blockIdx.x;
    const float* A = g_xn + (size_t)crow * BM * K;
    const float* Bm = g_wt_in + ccol * BN;
    float* C = g_xz + (size_t)crow * BM * N + ccol * BN;
    int tid = threadIdx.x;
    int tCol = tid & 15, tRow = tid >> 4;
    int irA = tid >> 1, icA = (tid & 1) << 2;
    int irB = tid >> 5, icB = (tid & 31) << 2;
    float acc[TM * TN] = {0.f};
    float rm[TM], rn[TN];
    for (int k0 = 0; k0 < K; k0 += BK) {
        float4 av = *(const float4*)(A + (size_t)irA * K + icA);
        As[(icA + 0) * BM + irA] = av.x;
        As[(icA + 1) * BM + irA] = av.y;
        As[(icA + 2) * BM + irA] = av.z;
        As[(icA + 3) * BM + irA] = av.w;
        *(float4*)(Bs + irB * BN + icB) = *(const float4*)(Bm + (size_t)irB * N + icB);
        __syncthreads();
        A += BK; Bm += (size_t)BK * N;
#pragma unroll
        for (int k = 0; k < BK; k++) {
#pragma unroll
            for (int i = 0; i < TM; i++) rm[i] = As[k * BM + tRow * TM + i];
#pragma unroll
            for (int j = 0; j < TN; j++) rn[j] = Bs[k * BN + tCol * TN + j];
#pragma unroll
            for (int i = 0; i < TM; i++)
#pragma unroll
                for (int j = 0; j < TN; j++) acc[i * TN + j] += rm[i] * rn[j];
        }
        __syncthreads();
    }
#pragma unroll
    for (int i = 0; i < TM; i++)
#pragma unroll
        for (int j = 0; j < TN; j += 4) {
            float4 v = make_float4(acc[i * TN + j], acc[i * TN + j + 1],
                                   acc[i * TN + j + 2], acc[i * TN + j + 3]);
            *(float4*)(C + (size_t)(tRow * TM + i) * N + tCol * TN + j) = v;
        }
}

// ---------------- causal conv (depthwise K=4) + SiLU, per direction ----------------
__global__ __launch_bounds__(256) void conv_silu_kernel(const float* __restrict__ cw_f,
                                                        const float* __restrict__ cb_f,
                                                        const float* __restrict__ cw_b,
                                                        const float* __restrict__ cb_b) {
    int dir = blockIdx.z;
    size_t i = (size_t)blockIdx.x * 256 + threadIdx.x;   // < BLr*DI
    int d = (int)(i % DI);
    size_t r = i / DI;
    int bb = (int)(r / Ll), l = (int)(r % Ll);
    const float* cw = dir ? cw_b : cw_f;
    float acc = (dir ? cb_b : cb_f)[d];
#pragma unroll
    for (int k = 0; k < 4; k++) {
        int lk = l - 3 + k;
        if (lk >= 0) {
            int op = dir ? (Ll - 1 - lk) : lk;
            acc += cw[d * 4 + k] * g_xz[((size_t)bb * Ll + op) * (2 * DI) + d];
        }
    }
    float s = acc * (1.f / (1.f + __expf(-acc)));
    g_xc[dir][i] = s;
}

// ---------------- x_proj: dbc = xc @ xproj_w^T  (N=56, K=768) ----------------
__global__ __launch_bounds__(256) void xproj_kernel(const float* __restrict__ xw_f,
                                                    const float* __restrict__ xw_b) {
    int dir = blockIdx.y;
    int r0 = blockIdx.x * 64;
    const float* W = dir ? xw_b : xw_f;        // (56,768)
    const float* X = g_xc[dir];
    __shared__ float Xs[64][33];
    __shared__ float Ws[56][33];
    int tid = threadIdx.x;
    int tRow = tid >> 3;      // 0..31 -> 2 rows each
    int tCol = tid & 7;       // 0..7  -> 7 cols each
    float acc[2][7];
#pragma unroll
    for (int a = 0; a < 2; a++)
#pragma unroll
        for (int j = 0; j < 7; j++) acc[a][j] = 0.f;

    for (int k0 = 0; k0 < DI; k0 += 32) {
        __syncthreads();
        for (int i = tid; i < 64 * 32; i += 256) {
            int rr = i >> 5, kk = i & 31;
            Xs[rr][kk] = X[(size_t)(r0 + rr) * DI + k0 + kk];
        }
        for (int i = tid; i < 56 * 32; i += 256) {
            int rr = i >> 5, kk = i & 31;
            Ws[rr][kk] = W[rr * DI + k0 + kk];
        }
        __syncthreads();
#pragma unroll
        for (int kk = 0; kk < 32; kk++) {
            float rm0 = Xs[tRow * 2 + 0][kk];
            float rm1 = Xs[tRow * 2 + 1][kk];
#pragma unroll
            for (int j = 0; j < 7; j++) {
                float wv = Ws[tCol * 7 + j][kk];
                acc[0][j] += rm0 * wv;
                acc[1][j] += rm1 * wv;
            }
        }
    }
#pragma unroll
    for (int a = 0; a < 2; a++)
#pragma unroll
        for (int j = 0; j < 7; j++)
            g_dbc[dir][(size_t)(r0 + tRow * 2 + a) * DBCW + tCol * 7 + j] = acc[a][j];
}

// ---------------- dt_proj + softplus: delta = softplus(dt @ dt_w^T + b) ----------------
__global__ __launch_bounds__(256) void dtproj_kernel(const float* __restrict__ dtw_f,
                                                     const float* __restrict__ dtb_f,
                                                     const float* __restrict__ dtw_b,
                                                     const float* __restrict__ dtb_b) {
    int dir = blockIdx.z;
    int col = blockIdx.x * 256 + threadIdx.x;  // 0..767 (grid.x=3)
    int r0 = blockIdx.y * 32;
    const float* Wd = dir ? dtw_b : dtw_f;     // (768,24)
    float w[DTR];
#pragma unroll
    for (int k = 0; k < DTR; k++) w[k] = Wd[col * DTR + k];
    float bias = (dir ? dtb_b : dtb_f)[col];
    __shared__ float sdt[32 * DTR];
    for (int i = threadIdx.x; i < 32 * DTR; i += 256) {
        int rr = i / DTR, kk = i % DTR;
        sdt[i] = g_dbc[dir][(size_t)(r0 + rr) * DBCW + kk];
    }
    __syncthreads();
    for (int rr = 0; rr < 32; rr++) {
        float acc = bias;
#pragma unroll
        for (int k = 0; k < DTR; k++) acc += sdt[rr * DTR + k] * w[k];
        float sp = (acc > 20.f) ? acc : log1pf(__expf(acc));
        g_delta[dir][(size_t)(r0 + rr) * DI + col] = sp;
    }
}

// ---------------- selective scan (sequential over L per channel) ----------------
__global__ __launch_bounds__(64) void scan_kernel(const float* __restrict__ Alog_f,
                                                  const float* __restrict__ Alog_b,
                                                  const float* __restrict__ Dv_f,
                                                  const float* __restrict__ Dv_b) {
    int dir = blockIdx.z;
    int bb = blockIdx.y;
    int d = blockIdx.x * 64 + threadIdx.x;
    const float* Alog = dir ? Alog_b : Alog_f;
    const float* Dvp  = dir ? Dv_b  : Dv_f;
    const float* delta = g_delta[dir] + (size_t)bb * Ll * DI + d;
    const float* u     = g_xc[dir]   + (size_t)bb * Ll * DI + d;
    const float* dbc   = g_dbc[dir]  + (size_t)bb * Ll * DBCW;
    const float* zb    = g_xz + (size_t)bb * Ll * (2 * DI) + DI + d;
    float* yout        = g_y[dir] + (size_t)bb * Ll * DI + d;

    float A[NS];
#pragma unroll
    for (int n = 0; n < NS; n++) A[n] = -__expf(Alog[d * NS + n]);
    // fast path: A[n] == (n+1)*A[0]  (true for the reference's A_log = log(1..16))
    bool fast = true;
#pragma unroll
    for (int n = 1; n < NS; n++)
        fast = fast && (fabsf(A[n] - (float)(n + 1) * A[0]) <= 1e-5f * fabsf(A[n]));
    float Dv = Dvp[d];

    __shared__ float sB[8][NS], sC[8][NS];
    float h[NS];
#pragma unroll
    for (int n = 0; n < NS; n++) h[n] = 0.f;

    for (int t0 = 0; t0 < Ll; t0 += 8) {
        float dl[8], ul[8], zl[8];
#pragma unroll
        for (int i = 0; i < 8; i++) {
            dl[i] = delta[(size_t)(t0 + i) * DI];
            ul[i] = u[(size_t)(t0 + i) * DI];
            int op = dir ? (Ll - 1 - (t0 + i)) : (t0 + i);
            zl[i] = zb[(size_t)op * (2 * DI)];
        }
        __syncthreads();
        for (int i = threadIdx.x; i < 256; i += 64) {
            int which = i >> 7, tt = (i >> 4) & 7, n = i & 15;
            float v = dbc[(size_t)(t0 + tt) * DBCW + DTR + which * NS + n];
            if (which) sC[tt][n] = v; else sB[tt][n] = v;
        }
        __syncthreads();
#pragma unroll
        for (int i = 0; i < 8; i++) {
            float dt = dl[i];
            float du = dt * ul[i];
            float y = 0.f;
            if (fast) {
                float q = __expf(dt * A[0]);
                float p = q;
#pragma unroll
                for (int n = 0; n < NS; n++) {
                    h[n] = h[n] * p + du * sB[i][n];
                    y += h[n] * sC[i][n];
                    p *= q;
                }
            } else {
#pragma unroll
                for (int n = 0; n < NS; n++) {
                    float dA = __expf(dt * A[n]);
                    h[n] = h[n] * dA + du * sB[i][n];
                    y += h[n] * sC[i][n];
                }
            }
            y += ul[i] * Dv;
            float z = zl[i];
            float sz = z * (1.f / (1.f + __expf(-z)));
            int op = dir ? (Ll - 1 - (t0 + i)) : (t0 + i);
            yout[(size_t)op * DI] = y * sz;
        }
    }
}

// ---------------- out = x + (yf+yr) @ wt_out  (M=16384,N=384,K=768) ----------------
__global__ __launch_bounds__(256) void sgemm_out(const float* __restrict__ xres,
                                                 float* __restrict__ out) {
    const int BM = 128, BN = 128, BK = 8, TM = 8, TN = 8;
    const int N = DM, K = DI;
    __shared__ float As[BK * BM], Bs[BK * BN];
    int crow = blockIdx.y, ccol = blockIdx.x;
    const float* A0 = g_y[0] + (size_t)crow * BM * K;
    const float* A1 = g_y[1] + (size_t)crow * BM * K;
    const float* Bm = g_wt_out + ccol * BN;
    int tid = threadIdx.x;
    int tCol = tid & 15, tRow = tid >> 4;
    int irA = tid >> 1, icA = (tid & 1) << 2;
    int irB = tid >> 5, icB = (tid & 31) << 2;
    float acc[TM * TN] = {0.f};
    float rm[TM], rn[TN];
    for (int k0 = 0; k0 < K; k0 += BK) {
        float4 a0 = *(const float4*)(A0 + (size_t)irA * K + icA);
        float4 a1 = *(const float4*)(A1 + (size_t)irA * K + icA);
        As[(icA + 0) * BM + irA] = a0.x + a1.x;
        As[(icA + 1) * BM + irA] = a0.y + a1.y;
        As[(icA + 2) * BM + irA] = a0.z + a1.z;
        As[(icA + 3) * BM + irA] = a0.w + a1.w;
        *(float4*)(Bs + irB * BN + icB) = *(const float4*)(Bm + (size_t)irB * N + icB);
        __syncthreads();
        A0 += BK; A1 += BK; Bm += (size_t)BK * N;
#pragma unroll
        for (int k = 0; k < BK; k++) {
#pragma unroll
            for (int i = 0; i < TM; i++) rm[i] = As[k * BM + tRow * TM + i];
#pragma unroll
            for (int j = 0; j < TN; j++) rn[j] = Bs[k * BN + tCol * TN + j];
#pragma unroll
            for (int i = 0; i < TM; i++)
#pragma unroll
                for (int j = 0; j < TN; j++) acc[i * TN + j] += rm[i] * rn[j];
        }
        __syncthreads();
    }
#pragma unroll
    for (int i = 0; i < TM; i++) {
        size_t row = (size_t)crow * BM + tRow * TM + i;
#pragma unroll
        for (int j = 0; j < TN; j++) {
            size_t col = (size_t)ccol * BN + tCol * TN + j;
            out[row * N + col] = acc[i * TN + j] + xres[row * N + col];
        }
    }
}

// ---------------- launch ----------------
extern "C" void kernel_launch(void* const* d_in, const int* in_sizes, int n_in,
                              void* d_out, int out_size) {
    const float* x        = (const float*)d_in[0];
    const float* ln_w     = (const float*)d_in[1];
    const float* ln_b     = (const float*)d_in[2];
    const float* in_proj  = (const float*)d_in[3];
    const float* out_proj = (const float*)d_in[4];
    const float* cw_f     = (const float*)d_in[5];
    const float* cb_f     = (const float*)d_in[6];
    const float* xw_f     = (const float*)d_in[7];
    const float* dtw_f    = (const float*)d_in[8];
    const float* dtb_f    = (const float*)d_in[9];
    const float* Alog_f   = (const float*)d_in[10];
    const float* Dv_f     = (const float*)d_in[11];
    const float* cw_b     = (const float*)d_in[12];
    const float* cb_b     = (const float*)d_in[13];
    const float* xw_b     = (const float*)d_in[14];
    const float* dtw_b    = (const float*)d_in[15];
    const float* dtb_b    = (const float*)d_in[16];
    const float* Alog_b   = (const float*)d_in[17];
    const float* Dv_b     = (const float*)d_in[18];
    float* out = (float*)d_out;

    ln_kernel<<<BLr, 384>>>(x, ln_w, ln_b);
    transpose_in<<<(1536 * 384 + 255) / 256, 256>>>(in_proj);
    transpose_out<<<(384 * 768 + 255) / 256, 256>>>(out_proj);
    sgemm_in<<<dim3(12, 128), 256>>>();
    conv_silu_kernel<<<dim3((BLr * DI) / 256, 1, 2), 256>>>(cw_f, cb_f, cw_b, cb_b);
    xproj_kernel<<<dim3(BLr / 64, 2), 256>>>(xw_f, xw_b);
    dtproj_kernel<<<dim3(3, BLr / 32, 2), 256>>>(dtw_f, dtb_f, dtw_b, dtb_b);
    scan_kernel<<<dim3(DI / 64, Bb, 2), 64>>>(Alog_f, Alog_b, Dv_f, Dv_b);
    sgemm_out<<<dim3(3, 128), 256>>>(x, out);
}

// round 4
// speedup vs baseline: 2.1526x; 2.1526x over previous
#include <cuda_runtime.h>
#include <cstdint>

#define Bb   16
#define Ll   1024
#define DM   384
#define DI   768
#define NS   16
#define DTR  24
#define DBCW 56            // DTR + 2*NS
#define BLr  16384         // Bb*Ll

// ---------------- scratch (device globals; no allocations) ----------------
__device__ float g_xn[BLr * (size_t)DM];
__device__ float g_wt_in[(size_t)DM * 2 * DI];        // (384,1536) K-major
__device__ float g_wt_out[(size_t)DI * DM];           // (768,384)  K-major
__device__ float g_wtx[2][(size_t)DI * 64];           // (768,64)   K-major, zero-padded N
__device__ float g_xz[(size_t)BLr * 2 * DI];
__device__ float g_xc[2][(size_t)BLr * DI];
__device__ float g_dbc[2][(size_t)BLr * DBCW];
__device__ float g_delta[2][(size_t)BLr * DI];
__device__ float g_y[2][(size_t)BLr * DI];

// ---------------- tf32 mma helpers ----------------
__device__ __forceinline__ uint32_t f2tf(float x) {
    uint32_t r; asm("cvt.rna.tf32.f32 %0, %1;" : "=r"(r) : "f"(x)); return r;
}
__device__ __forceinline__ void mma_tf32(float (&d)[4], const uint32_t (&a)[4], const uint32_t (&b)[2]) {
    asm volatile("mma.sync.aligned.m16n8k8.row.col.f32.tf32.tf32.f32 "
                 "{%0,%1,%2,%3}, {%4,%5,%6,%7}, {%8,%9}, {%0,%1,%2,%3};"
                 : "+f"(d[0]), "+f"(d[1]), "+f"(d[2]), "+f"(d[3])
                 : "r"(a[0]), "r"(a[1]), "r"(a[2]), "r"(a[3]), "r"(b[0]), "r"(b[1]));
}

// ---------------- LayerNorm ----------------
__global__ __launch_bounds__(384) void ln_kernel(const float* __restrict__ x,
                                                 const float* __restrict__ w,
                                                 const float* __restrict__ b) {
    int r = blockIdx.x, t = threadIdx.x;
    float v = x[(size_t)r * DM + t];
    float s = v, s2 = v * v;
#pragma unroll
    for (int o = 16; o; o >>= 1) {
        s  += __shfl_xor_sync(0xffffffffu, s, o);
        s2 += __shfl_xor_sync(0xffffffffu, s2, o);
    }
    __shared__ float ps[12], ps2[12];
    __shared__ float smu, srstd;
    if ((t & 31) == 0) { ps[t >> 5] = s; ps2[t >> 5] = s2; }
    __syncthreads();
    if (t == 0) {
        float a = 0.f, a2 = 0.f;
#pragma unroll
        for (int i = 0; i < 12; i++) { a += ps[i]; a2 += ps2[i]; }
        float mu = a / DM;
        float var = a2 / DM - mu * mu;
        smu = mu; srstd = rsqrtf(var + 1e-5f);
    }
    __syncthreads();
    g_xn[(size_t)r * DM + t] = (v - smu) * srstd * w[t] + b[t];
}

// ---------------- weight transposes ----------------
__global__ void transpose_in(const float* __restrict__ W) {
    int i = blockIdx.x * 256 + threadIdx.x;
    if (i < 1536 * 384) { int n = i / 384, k = i % 384; g_wt_in[(size_t)k * 1536 + n] = W[i]; }
}
__global__ void transpose_out(const float* __restrict__ W) {
    int i = blockIdx.x * 256 + threadIdx.x;
    if (i < 384 * 768) { int n = i / 768, k = i % 768; g_wt_out[(size_t)k * 384 + n] = W[i]; }
}
__global__ void transpose_x(const float* __restrict__ Wf, const float* __restrict__ Wb) {
    int i = blockIdx.x * 256 + threadIdx.x;   // over 768*64
    if (i < 768 * 64) {
        int k = i / 64, n = i % 64;
        g_wtx[0][i] = (n < 56) ? Wf[n * 768 + k] : 0.f;
        g_wtx[1][i] = (n < 56) ? Wb[n * 768 + k] : 0.f;
    }
}

// ---------------- mm_in: xz = xn @ wt_in  (M=16384,N=1536,K=384), tf32 ----------------
__global__ __launch_bounds__(256, 2) void mm_in_tf32() {
    const int K = 384, N = 1536;
    __shared__ uint32_t As[128][20];
    __shared__ uint32_t Bs[16][136];
    int tid = threadIdx.x, lane = tid & 31, wid = tid >> 5;
    int wr = (wid & 3) * 32, wc = (wid >> 2) * 64;
    int g = lane >> 2, tg = lane & 3;
    const float* A  = g_xn + (size_t)blockIdx.y * 128 * K;
    const float* Bt = g_wt_in + blockIdx.x * 128;
    float acc[2][8][4];
#pragma unroll
    for (int mi = 0; mi < 2; mi++)
#pragma unroll
        for (int ni = 0; ni < 8; ni++)
#pragma unroll
            for (int q = 0; q < 4; q++) acc[mi][ni][q] = 0.f;

    for (int k0 = 0; k0 < K; k0 += 16) {
#pragma unroll
        for (int i = 0; i < 2; i++) {
            int idx = tid + i * 256;
            int r = idx >> 2, c4 = (idx & 3) * 4;
            float4 v = *(const float4*)(A + (size_t)r * K + k0 + c4);
            As[r][c4 + 0] = f2tf(v.x); As[r][c4 + 1] = f2tf(v.y);
            As[r][c4 + 2] = f2tf(v.z); As[r][c4 + 3] = f2tf(v.w);
        }
#pragma unroll
        for (int i = 0; i < 2; i++) {
            int idx = tid + i * 256;
            int kk = idx >> 5, n4 = (idx & 31) * 4;
            float4 v = *(const float4*)(Bt + (size_t)(k0 + kk) * N + n4);
            Bs[kk][n4 + 0] = f2tf(v.x); Bs[kk][n4 + 1] = f2tf(v.y);
            Bs[kk][n4 + 2] = f2tf(v.z); Bs[kk][n4 + 3] = f2tf(v.w);
        }
        __syncthreads();
#pragma unroll
        for (int ks = 0; ks < 2; ks++) {
            int kb = ks * 8;
            uint32_t af[2][4], bf[8][2];
#pragma unroll
            for (int mi = 0; mi < 2; mi++) {
                int r0 = wr + mi * 16;
                af[mi][0] = As[r0 + g][kb + tg];
                af[mi][1] = As[r0 + g + 8][kb + tg];
                af[mi][2] = As[r0 + g][kb + tg + 4];
                af[mi][3] = As[r0 + g + 8][kb + tg + 4];
            }
#pragma unroll
            for (int ni = 0; ni < 8; ni++) {
                bf[ni][0] = Bs[kb + tg][wc + ni * 8 + g];
                bf[ni][1] = Bs[kb + tg + 4][wc + ni * 8 + g];
            }
#pragma unroll
            for (int mi = 0; mi < 2; mi++)
#pragma unroll
                for (int ni = 0; ni < 8; ni++) mma_tf32(acc[mi][ni], af[mi], bf[ni]);
        }
        __syncthreads();
    }
    float* C = g_xz + (size_t)(blockIdx.y * 128) * N + blockIdx.x * 128;
#pragma unroll
    for (int mi = 0; mi < 2; mi++)
#pragma unroll
        for (int ni = 0; ni < 8; ni++) {
            int r = wr + mi * 16 + g, c = wc + ni * 8 + tg * 2;
            *(float2*)(C + (size_t)r * N + c)       = make_float2(acc[mi][ni][0], acc[mi][ni][1]);
            *(float2*)(C + (size_t)(r + 8) * N + c) = make_float2(acc[mi][ni][2], acc[mi][ni][3]);
        }
}

// ---------------- mm_out: out = x + (yf+yr) @ wt_out (M=16384,N=384,K=768), tf32 ----------------
__global__ __launch_bounds__(256, 2) void mm_out_tf32(const float* __restrict__ xres,
                                                      float* __restrict__ out) {
    const int K = 768, N = 384;
    __shared__ uint32_t As[128][20];
    __shared__ uint32_t Bs[16][136];
    int tid = threadIdx.x, lane = tid & 31, wid = tid >> 5;
    int wr = (wid & 3) * 32, wc = (wid >> 2) * 64;
    int g = lane >> 2, tg = lane & 3;
    const float* A0 = g_y[0] + (size_t)blockIdx.y * 128 * K;
    const float* A1 = g_y[1] + (size_t)blockIdx.y * 128 * K;
    const float* Bt = g_wt_out + blockIdx.x * 128;
    float acc[2][8][4];
#pragma unroll
    for (int mi = 0; mi < 2; mi++)
#pragma unroll
        for (int ni = 0; ni < 8; ni++)
#pragma unroll
            for (int q = 0; q < 4; q++) acc[mi][ni][q] = 0.f;

    for (int k0 = 0; k0 < K; k0 += 16) {
#pragma unroll
        for (int i = 0; i < 2; i++) {
            int idx = tid + i * 256;
            int r = idx >> 2, c4 = (idx & 3) * 4;
            float4 v0 = *(const float4*)(A0 + (size_t)r * K + k0 + c4);
            float4 v1 = *(const float4*)(A1 + (size_t)r * K + k0 + c4);
            As[r][c4 + 0] = f2tf(v0.x + v1.x); As[r][c4 + 1] = f2tf(v0.y + v1.y);
            As[r][c4 + 2] = f2tf(v0.z + v1.z); As[r][c4 + 3] = f2tf(v0.w + v1.w);
        }
#pragma unroll
        for (int i = 0; i < 2; i++) {
            int idx = tid + i * 256;
            int kk = idx >> 5, n4 = (idx & 31) * 4;
            float4 v = *(const float4*)(Bt + (size_t)(k0 + kk) * N + n4);
            Bs[kk][n4 + 0] = f2tf(v.x); Bs[kk][n4 + 1] = f2tf(v.y);
            Bs[kk][n4 + 2] = f2tf(v.z); Bs[kk][n4 + 3] = f2tf(v.w);
        }
        __syncthreads();
#pragma unroll
        for (int ks = 0; ks < 2; ks++) {
            int kb = ks * 8;
            uint32_t af[2][4], bf[8][2];
#pragma unroll
            for (int mi = 0; mi < 2; mi++) {
                int r0 = wr + mi * 16;
                af[mi][0] = As[r0 + g][kb + tg];
                af[mi][1] = As[r0 + g + 8][kb + tg];
                af[mi][2] = As[r0 + g][kb + tg + 4];
                af[mi][3] = As[r0 + g + 8][kb + tg + 4];
            }
#pragma unroll
            for (int ni = 0; ni < 8; ni++) {
                bf[ni][0] = Bs[kb + tg][wc + ni * 8 + g];
                bf[ni][1] = Bs[kb + tg + 4][wc + ni * 8 + g];
            }
#pragma unroll
            for (int mi = 0; mi < 2; mi++)
#pragma unroll
                for (int ni = 0; ni < 8; ni++) mma_tf32(acc[mi][ni], af[mi], bf[ni]);
        }
        __syncthreads();
    }
    size_t rbase = (size_t)blockIdx.y * 128;
    int cbase = blockIdx.x * 128;
#pragma unroll
    for (int mi = 0; mi < 2; mi++)
#pragma unroll
        for (int ni = 0; ni < 8; ni++) {
            int r = wr + mi * 16 + g, c = wc + ni * 8 + tg * 2;
            size_t o0 = (rbase + r) * N + cbase + c;
            size_t o1 = (rbase + r + 8) * N + cbase + c;
            out[o0]     = acc[mi][ni][0] + xres[o0];
            out[o0 + 1] = acc[mi][ni][1] + xres[o0 + 1];
            out[o1]     = acc[mi][ni][2] + xres[o1];
            out[o1 + 1] = acc[mi][ni][3] + xres[o1 + 1];
        }
}

// ---------------- mm_x: dbc = xc @ wtx (M=16384,N=64(->56),K=768), tf32 ----------------
__global__ __launch_bounds__(256, 2) void mm_x_tf32() {
    const int K = 768;
    int dir = blockIdx.z;
    __shared__ uint32_t As[128][20];
    __shared__ uint32_t Bs[16][72];
    int tid = threadIdx.x, lane = tid & 31, wid = tid >> 5;
    int wr = wid * 16;
    int g = lane >> 2, tg = lane & 3;
    const float* A  = g_xc[dir] + (size_t)blockIdx.y * 128 * K;
    const float* Bt = g_wtx[dir];
    float acc[8][4];
#pragma unroll
    for (int ni = 0; ni < 8; ni++)
#pragma unroll
        for (int q = 0; q < 4; q++) acc[ni][q] = 0.f;

    for (int k0 = 0; k0 < K; k0 += 16) {
#pragma unroll
        for (int i = 0; i < 2; i++) {
            int idx = tid + i * 256;
            int r = idx >> 2, c4 = (idx & 3) * 4;
            float4 v = *(const float4*)(A + (size_t)r * K + k0 + c4);
            As[r][c4 + 0] = f2tf(v.x); As[r][c4 + 1] = f2tf(v.y);
            As[r][c4 + 2] = f2tf(v.z); As[r][c4 + 3] = f2tf(v.w);
        }
        {
            int kk = tid >> 4, n4 = (tid & 15) * 4;
            float4 v = *(const float4*)(Bt + (size_t)(k0 + kk) * 64 + n4);
            Bs[kk][n4 + 0] = f2tf(v.x); Bs[kk][n4 + 1] = f2tf(v.y);
            Bs[kk][n4 + 2] = f2tf(v.z); Bs[kk][n4 + 3] = f2tf(v.w);
        }
        __syncthreads();
#pragma unroll
        for (int ks = 0; ks < 2; ks++) {
            int kb = ks * 8;
            uint32_t af[4], bf[8][2];
            af[0] = As[wr + g][kb + tg];
            af[1] = As[wr + g + 8][kb + tg];
            af[2] = As[wr + g][kb + tg + 4];
            af[3] = As[wr + g + 8][kb + tg + 4];
#pragma unroll
            for (int ni = 0; ni < 8; ni++) {
                bf[ni][0] = Bs[kb + tg][ni * 8 + g];
                bf[ni][1] = Bs[kb + tg + 4][ni * 8 + g];
            }
#pragma unroll
            for (int ni = 0; ni < 8; ni++) mma_tf32(acc[ni], af, bf[ni]);
        }
        __syncthreads();
    }
    size_t rbase = (size_t)blockIdx.y * 128;
#pragma unroll
    for (int ni = 0; ni < 8; ni++) {
        int c = ni * 8 + tg * 2;
        if (c < 56) {
            int r = wr + g;
            float* o0 = g_dbc[dir] + (rbase + r) * DBCW + c;
            float* o1 = g_dbc[dir] + (rbase + r + 8) * DBCW + c;
            o0[0] = acc[ni][0]; o0[1] = acc[ni][1];
            o1[0] = acc[ni][2]; o1[1] = acc[ni][3];
        }
    }
}

// ---------------- causal conv (rolling registers) + SiLU ----------------
__global__ __launch_bounds__(256) void conv_roll_kernel(const float* __restrict__ cw_f,
                                                        const float* __restrict__ cb_f,
                                                        const float* __restrict__ cw_b,
                                                        const float* __restrict__ cb_b) {
    int dir = blockIdx.z;
    int bb = blockIdx.y;
    int d = blockIdx.x * 256 + threadIdx.x;
    const float* cw = dir ? cw_b : cw_f;
    float w0 = cw[d * 4 + 0], w1 = cw[d * 4 + 1], w2 = cw[d * 4 + 2], w3 = cw[d * 4 + 3];
    float bias = (dir ? cb_b : cb_f)[d];
    const float* xz = g_xz + (size_t)bb * Ll * (2 * DI) + d;
    float* yo = g_xc[dir] + (size_t)bb * Ll * DI + d;
    float x1 = 0.f, x2 = 0.f, x3 = 0.f;   // x_{l-1}, x_{l-2}, x_{l-3}
    for (int l = 0; l < Ll; l += 4) {
        float xv[4];
#pragma unroll
        for (int j = 0; j < 4; j++) {
            int lp = dir ? (Ll - 1 - (l + j)) : (l + j);
            xv[j] = xz[(size_t)lp * (2 * DI)];
        }
#pragma unroll
        for (int j = 0; j < 4; j++) {
            float a = bias + w3 * xv[j] + w2 * x1 + w1 * x2 + w0 * x3;
            x3 = x2; x2 = x1; x1 = xv[j];
            float s = a * (1.f / (1.f + __expf(-a)));
            yo[(size_t)(l + j) * DI] = s;
        }
    }
}

// ---------------- dt_proj + softplus ----------------
__global__ __launch_bounds__(256) void dtproj_kernel(const float* __restrict__ dtw_f,
                                                     const float* __restrict__ dtb_f,
                                                     const float* __restrict__ dtw_b,
                                                     const float* __restrict__ dtb_b) {
    int dir = blockIdx.z;
    int col = blockIdx.x * 256 + threadIdx.x;
    int r0 = blockIdx.y * 32;
    const float* Wd = dir ? dtw_b : dtw_f;
    float w[DTR];
#pragma unroll
    for (int k = 0; k < DTR; k++) w[k] = Wd[col * DTR + k];
    float bias = (dir ? dtb_b : dtb_f)[col];
    __shared__ float sdt[32 * DTR];
    for (int i = threadIdx.x; i < 32 * DTR; i += 256) {
        int rr = i / DTR, kk = i % DTR;
        sdt[i] = g_dbc[dir][(size_t)(r0 + rr) * DBCW + kk];
    }
    __syncthreads();
    for (int rr = 0; rr < 32; rr++) {
        float acc = bias;
#pragma unroll
        for (int k = 0; k < DTR; k++) acc += sdt[rr * DTR + k] * w[k];
        float sp = (acc > 20.f) ? acc : log1pf(__expf(acc));
        g_delta[dir][(size_t)(r0 + rr) * DI + col] = sp;
    }
}

// ---------------- selective scan ----------------
__global__ __launch_bounds__(64) void scan_kernel(const float* __restrict__ Alog_f,
                                                  const float* __restrict__ Alog_b,
                                                  const float* __restrict__ Dv_f,
                                                  const float* __restrict__ Dv_b) {
    int dir = blockIdx.z;
    int bb = blockIdx.y;
    int d = blockIdx.x * 64 + threadIdx.x;
    const float* Alog = dir ? Alog_b : Alog_f;
    const float* Dvp  = dir ? Dv_b  : Dv_f;
    const float* delta = g_delta[dir] + (size_t)bb * Ll * DI + d;
    const float* u     = g_xc[dir]   + (size_t)bb * Ll * DI + d;
    const float* dbc   = g_dbc[dir]  + (size_t)bb * Ll * DBCW;
    const float* zb    = g_xz + (size_t)bb * Ll * (2 * DI) + DI + d;
    float* yout        = g_y[dir] + (size_t)bb * Ll * DI + d;

    float A[NS];
#pragma unroll
    for (int n = 0; n < NS; n++) A[n] = -__expf(Alog[d * NS + n]);
    bool fast = true;
#pragma unroll
    for (int n = 1; n < NS; n++)
        fast = fast && (fabsf(A[n] - (float)(n + 1) * A[0]) <= 1e-5f * fabsf(A[n]));
    float Dv = Dvp[d];

    __shared__ float sB[8][NS], sC[8][NS];
    float h[NS];
#pragma unroll
    for (int n = 0; n < NS; n++) h[n] = 0.f;

    for (int t0 = 0; t0 < Ll; t0 += 8) {
        float dl[8], ul[8], zl[8], ql[8];
#pragma unroll
        for (int i = 0; i < 8; i++) {
            dl[i] = delta[(size_t)(t0 + i) * DI];
            ul[i] = u[(size_t)(t0 + i) * DI];
            int op = dir ? (Ll - 1 - (t0 + i)) : (t0 + i);
            zl[i] = zb[(size_t)op * (2 * DI)];
            ql[i] = __expf(dl[i] * A[0]);    // only used on fast path; independent of h
        }
        __syncthreads();
        for (int i = threadIdx.x; i < 256; i += 64) {
            int which = i >> 7, tt = (i >> 4) & 7, n = i & 15;
            float v = dbc[(size_t)(t0 + tt) * DBCW + DTR + which * NS + n];
            if (which) sC[tt][n] = v; else sB[tt][n] = v;
        }
        __syncthreads();
#pragma unroll
        for (int i = 0; i < 8; i++) {
            float dt = dl[i];
            float du = dt * ul[i];
            float y = 0.f;
            if (fast) {
                // log-depth power tree: pw[n] = q^(n+1)
                float q = ql[i];
                float q2 = q * q, q4 = q2 * q2, q8 = q4 * q4;
                float q3 = q2 * q, q5 = q4 * q, q6 = q4 * q2, q7 = q4 * q3;
                float pw[NS];
                pw[0] = q;       pw[1] = q2;      pw[2] = q3;      pw[3] = q4;
                pw[4] = q5;      pw[5] = q6;      pw[6] = q7;      pw[7] = q8;
                pw[8] = q8 * q;  pw[9] = q8 * q2; pw[10] = q8 * q3; pw[11] = q8 * q4;
                pw[12] = q8 * q5; pw[13] = q8 * q6; pw[14] = q8 * q7; pw[15] = q8 * q8;
#pragma unroll
                for (int n = 0; n < NS; n++) {
                    h[n] = h[n] * pw[n] + du * sB[i][n];
                    y += h[n] * sC[i][n];
                }
            } else {
#pragma unroll
                for (int n = 0; n < NS; n++) {
                    float dA = __expf(dt * A[n]);
                    h[n] = h[n] * dA + du * sB[i][n];
                    y += h[n] * sC[i][n];
                }
            }
            y += ul[i] * Dv;
            float z = zl[i];
            float sz = z * (1.f / (1.f + __expf(-z)));
            int op = dir ? (Ll - 1 - (t0 + i)) : (t0 + i);
            yout[(size_t)op * DI] = y * sz;
        }
    }
}

// ---------------- launch ----------------
extern "C" void kernel_launch(void* const* d_in, const int* in_sizes, int n_in,
                              void* d_out, int out_size) {
    const float* x        = (const float*)d_in[0];
    const float* ln_w     = (const float*)d_in[1];
    const float* ln_b     = (const float*)d_in[2];
    const float* in_proj  = (const float*)d_in[3];
    const float* out_proj = (const float*)d_in[4];
    const float* cw_f     = (const float*)d_in[5];
    const float* cb_f     = (const float*)d_in[6];
    const float* xw_f     = (const float*)d_in[7];
    const float* dtw_f    = (const float*)d_in[8];
    const float* dtb_f    = (const float*)d_in[9];
    const float* Alog_f   = (const float*)d_in[10];
    const float* Dv_f     = (const float*)d_in[11];
    const float* cw_b     = (const float*)d_in[12];
    const float* cb_b     = (const float*)d_in[13];
    const float* xw_b     = (const float*)d_in[14];
    const float* dtw_b    = (const float*)d_in[15];
    const float* dtb_b    = (const float*)d_in[16];
    const float* Alog_b   = (const float*)d_in[17];
    const float* Dv_b     = (const float*)d_in[18];
    float* out = (float*)d_out;

    ln_kernel<<<BLr, 384>>>(x, ln_w, ln_b);
    transpose_in<<<(1536 * 384 + 255) / 256, 256>>>(in_proj);
    transpose_out<<<(384 * 768 + 255) / 256, 256>>>(out_proj);
    transpose_x<<<(768 * 64 + 255) / 256, 256>>>(xw_f, xw_b);
    mm_in_tf32<<<dim3(12, 128), 256>>>();
    conv_roll_kernel<<<dim3(3, Bb, 2), 256>>>(cw_f, cb_f, cw_b, cb_b);
    mm_x_tf32<<<dim3(1, 128, 2), 256>>>();
    dtproj_kernel<<<dim3(3, BLr / 32, 2), 256>>>(dtw_f, dtb_f, dtw_b, dtb_b);
    scan_kernel<<<dim3(DI / 64, Bb, 2), 64>>>(Alog_f, Alog_b, Dv_f, Dv_b);
    mm_out_tf32<<<dim3(3, 128), 256>>>(x, out);
}

// round 5
// speedup vs baseline: 2.8950x; 1.3449x over previous
#include <cuda_runtime.h>
#include <cstdint>

#define Bb   16
#define Ll   1024
#define DM   384
#define DI   768
#define NS   16
#define DTR  24
#define DBCW 56            // DTR + 2*NS
#define BLr  16384         // Bb*Ll
#define NCH  8             // scan chunks
#define CHT  128           // steps per chunk

// ---------------- scratch (device globals; no allocations) ----------------
__device__ float    g_xn[BLr * (size_t)DM];
__device__ uint32_t g_win_p[(size_t)(DM / 2) * 1536];   // bf16x2 pairs along k: [k2][n]
__device__ uint32_t g_wout_p[(size_t)(DI / 2) * DM];    // [k2=384][n=384]
__device__ uint32_t g_wx_p[2][(size_t)(DI / 2) * 64];   // [k2=384][n=64], zero-padded
__device__ float    g_xz[(size_t)BLr * 2 * DI];
__device__ float    g_xc[2][(size_t)BLr * DI];
__device__ float    g_dbc[2][(size_t)BLr * DBCW];
__device__ float    g_delta[2][(size_t)BLr * DI];
__device__ float    g_y[2][(size_t)BLr * DI];
__device__ float    g_hc[2][Bb][NCH][NS][DI];           // chunk states
__device__ float    g_dts[2][Bb][NCH][DI];              // per-chunk sum of dt

// ---------------- bf16 helpers ----------------
__device__ __forceinline__ uint32_t pack_bf2(float lo, float hi) {
    uint32_t r; asm("cvt.rn.bf16x2.f32 %0, %1, %2;" : "=r"(r) : "f"(hi), "f"(lo)); return r;
}
__device__ __forceinline__ void mma_bf16(float (&d)[4], const uint32_t (&a)[4], const uint32_t (&b)[2]) {
    asm volatile("mma.sync.aligned.m16n8k16.row.col.f32.bf16.bf16.f32 "
                 "{%0,%1,%2,%3}, {%4,%5,%6,%7}, {%8,%9}, {%0,%1,%2,%3};"
                 : "+f"(d[0]), "+f"(d[1]), "+f"(d[2]), "+f"(d[3])
                 : "r"(a[0]), "r"(a[1]), "r"(a[2]), "r"(a[3]), "r"(b[0]), "r"(b[1]));
}

// ---------------- LayerNorm ----------------
__global__ __launch_bounds__(384) void ln_kernel(const float* __restrict__ x,
                                                 const float* __restrict__ w,
                                                 const float* __restrict__ b) {
    int r = blockIdx.x, t = threadIdx.x;
    float v = x[(size_t)r * DM + t];
    float s = v, s2 = v * v;
#pragma unroll
    for (int o = 16; o; o >>= 1) {
        s  += __shfl_xor_sync(0xffffffffu, s, o);
        s2 += __shfl_xor_sync(0xffffffffu, s2, o);
    }
    __shared__ float ps[12], ps2[12];
    __shared__ float smu, srstd;
    if ((t & 31) == 0) { ps[t >> 5] = s; ps2[t >> 5] = s2; }
    __syncthreads();
    if (t == 0) {
        float a = 0.f, a2 = 0.f;
#pragma unroll
        for (int i = 0; i < 12; i++) { a += ps[i]; a2 += ps2[i]; }
        float mu = a / DM;
        float var = a2 / DM - mu * mu;
        smu = mu; srstd = rsqrtf(var + 1e-5f);
    }
    __syncthreads();
    g_xn[(size_t)r * DM + t] = (v - smu) * srstd * w[t] + b[t];
}

// ---------------- weight transposes + bf16 packing ----------------
__global__ void transpose_in(const float* __restrict__ W) {   // (1536,384) -> pairs [192][1536]
    int i = blockIdx.x * 256 + threadIdx.x;
    if (i < 192 * 1536) {
        int k2 = i / 1536, n = i % 1536;
        float2 v = *(const float2*)(W + (size_t)n * 384 + 2 * k2);
        g_win_p[i] = pack_bf2(v.x, v.y);
    }
}
__global__ void transpose_out(const float* __restrict__ W) {  // (384,768) -> pairs [384][384]
    int i = blockIdx.x * 256 + threadIdx.x;
    if (i < 384 * 384) {
        int k2 = i / 384, n = i % 384;
        float2 v = *(const float2*)(W + (size_t)n * 768 + 2 * k2);
        g_wout_p[i] = pack_bf2(v.x, v.y);
    }
}
__global__ void transpose_x(const float* __restrict__ Wf, const float* __restrict__ Wb) {
    int i = blockIdx.x * 256 + threadIdx.x;   // over 384*64
    if (i < 384 * 64) {
        int k2 = i / 64, n = i % 64;
        if (n < 56) {
            float2 vf = *(const float2*)(Wf + (size_t)n * 768 + 2 * k2);
            float2 vb = *(const float2*)(Wb + (size_t)n * 768 + 2 * k2);
            g_wx_p[0][i] = pack_bf2(vf.x, vf.y);
            g_wx_p[1][i] = pack_bf2(vb.x, vb.y);
        } else {
            g_wx_p[0][i] = 0u; g_wx_p[1][i] = 0u;
        }
    }
}

// ---------------- mm_in: xz = xn @ Win  (M=16384,N=1536,K=384), bf16 ----------------
__global__ __launch_bounds__(256, 2) void mm_in_bf16() {
    const int K = 384, N = 1536;
    __shared__ uint32_t As[128][17];    // [row][k2 local 0..15]
    __shared__ uint32_t Bs[16][136];    // [k2 local][n local]
    int tid = threadIdx.x, lane = tid & 31, wid = tid >> 5;
    int wr = (wid & 3) * 32, wc = (wid >> 2) * 64;
    int g = lane >> 2, tg = lane & 3;
    const float* A = g_xn + (size_t)blockIdx.y * 128 * K;
    const uint32_t* Bp = g_win_p + blockIdx.x * 128;
    float acc[2][8][4];
#pragma unroll
    for (int mi = 0; mi < 2; mi++)
#pragma unroll
        for (int ni = 0; ni < 8; ni++)
#pragma unroll
            for (int q = 0; q < 4; q++) acc[mi][ni][q] = 0.f;

    for (int k0 = 0; k0 < K; k0 += 32) {
#pragma unroll
        for (int i = 0; i < 4; i++) {
            int idx = tid + i * 256;
            int r = idx >> 3, f4 = idx & 7;
            float4 v = *(const float4*)(A + (size_t)r * K + k0 + f4 * 4);
            As[r][f4 * 2 + 0] = pack_bf2(v.x, v.y);
            As[r][f4 * 2 + 1] = pack_bf2(v.z, v.w);
        }
#pragma unroll
        for (int i = 0; i < 2; i++) {
            int idx = tid + i * 256;
            int kk = idx >> 5, n4 = (idx & 31) * 4;
            *(uint4*)&Bs[kk][n4] = *(const uint4*)(Bp + (size_t)(k0 / 2 + kk) * N + n4);
        }
        __syncthreads();
#pragma unroll
        for (int ks = 0; ks < 2; ks++) {
            int kb2 = ks * 8;
            uint32_t af[2][4], bf[8][2];
#pragma unroll
            for (int mi = 0; mi < 2; mi++) {
                int r0 = wr + mi * 16;
                af[mi][0] = As[r0 + g][kb2 + tg];
                af[mi][1] = As[r0 + g + 8][kb2 + tg];
                af[mi][2] = As[r0 + g][kb2 + tg + 4];
                af[mi][3] = As[r0 + g + 8][kb2 + tg + 4];
            }
#pragma unroll
            for (int ni = 0; ni < 8; ni++) {
                bf[ni][0] = Bs[kb2 + tg][wc + ni * 8 + g];
                bf[ni][1] = Bs[kb2 + tg + 4][wc + ni * 8 + g];
            }
#pragma unroll
            for (int mi = 0; mi < 2; mi++)
#pragma unroll
                for (int ni = 0; ni < 8; ni++) mma_bf16(acc[mi][ni], af[mi], bf[ni]);
        }
        __syncthreads();
    }
    float* C = g_xz + (size_t)(blockIdx.y * 128) * N + blockIdx.x * 128;
#pragma unroll
    for (int mi = 0; mi < 2; mi++)
#pragma unroll
        for (int ni = 0; ni < 8; ni++) {
            int r = wr + mi * 16 + g, c = wc + ni * 8 + tg * 2;
            *(float2*)(C + (size_t)r * N + c)       = make_float2(acc[mi][ni][0], acc[mi][ni][1]);
            *(float2*)(C + (size_t)(r + 8) * N + c) = make_float2(acc[mi][ni][2], acc[mi][ni][3]);
        }
}

// ---------------- mm_out: out = x + (yf+yr) @ Wout (M=16384,N=384,K=768), bf16 ----------------
__global__ __launch_bounds__(256, 2) void mm_out_bf16(const float* __restrict__ xres,
                                                      float* __restrict__ out) {
    const int K = 768, N = 384;
    __shared__ uint32_t As[128][17];
    __shared__ uint32_t Bs[16][136];
    int tid = threadIdx.x, lane = tid & 31, wid = tid >> 5;
    int wr = (wid & 3) * 32, wc = (wid >> 2) * 64;
    int g = lane >> 2, tg = lane & 3;
    const float* A0 = g_y[0] + (size_t)blockIdx.y * 128 * K;
    const float* A1 = g_y[1] + (size_t)blockIdx.y * 128 * K;
    const uint32_t* Bp = g_wout_p + blockIdx.x * 128;
    float acc[2][8][4];
#pragma unroll
    for (int mi = 0; mi < 2; mi++)
#pragma unroll
        for (int ni = 0; ni < 8; ni++)
#pragma unroll
            for (int q = 0; q < 4; q++) acc[mi][ni][q] = 0.f;

    for (int k0 = 0; k0 < K; k0 += 32) {
#pragma unroll
        for (int i = 0; i < 4; i++) {
            int idx = tid + i * 256;
            int r = idx >> 3, f4 = idx & 7;
            float4 v0 = *(const float4*)(A0 + (size_t)r * K + k0 + f4 * 4);
            float4 v1 = *(const float4*)(A1 + (size_t)r * K + k0 + f4 * 4);
            As[r][f4 * 2 + 0] = pack_bf2(v0.x + v1.x, v0.y + v1.y);
            As[r][f4 * 2 + 1] = pack_bf2(v0.z + v1.z, v0.w + v1.w);
        }
#pragma unroll
        for (int i = 0; i < 2; i++) {
            int idx = tid + i * 256;
            int kk = idx >> 5, n4 = (idx & 31) * 4;
            *(uint4*)&Bs[kk][n4] = *(const uint4*)(Bp + (size_t)(k0 / 2 + kk) * N + n4);
        }
        __syncthreads();
#pragma unroll
        for (int ks = 0; ks < 2; ks++) {
            int kb2 = ks * 8;
            uint32_t af[2][4], bf[8][2];
#pragma unroll
            for (int mi = 0; mi < 2; mi++) {
                int r0 = wr + mi * 16;
                af[mi][0] = As[r0 + g][kb2 + tg];
                af[mi][1] = As[r0 + g + 8][kb2 + tg];
                af[mi][2] = As[r0 + g][kb2 + tg + 4];
                af[mi][3] = As[r0 + g + 8][kb2 + tg + 4];
            }
#pragma unroll
            for (int ni = 0; ni < 8; ni++) {
                bf[ni][0] = Bs[kb2 + tg][wc + ni * 8 + g];
                bf[ni][1] = Bs[kb2 + tg + 4][wc + ni * 8 + g];
            }
#pragma unroll
            for (int mi = 0; mi < 2; mi++)
#pragma unroll
                for (int ni = 0; ni < 8; ni++) mma_bf16(acc[mi][ni], af[mi], bf[ni]);
        }
        __syncthreads();
    }
    size_t rbase = (size_t)blockIdx.y * 128;
    int cbase = blockIdx.x * 128;
#pragma unroll
    for (int mi = 0; mi < 2; mi++)
#pragma unroll
        for (int ni = 0; ni < 8; ni++) {
            int r = wr + mi * 16 + g, c = wc + ni * 8 + tg * 2;
            size_t o0 = (rbase + r) * N + cbase + c;
            size_t o1 = (rbase + r + 8) * N + cbase + c;
            out[o0]     = acc[mi][ni][0] + xres[o0];
            out[o0 + 1] = acc[mi][ni][1] + xres[o0 + 1];
            out[o1]     = acc[mi][ni][2] + xres[o1];
            out[o1 + 1] = acc[mi][ni][3] + xres[o1 + 1];
        }
}

// ---------------- mm_x: dbc = xc @ Wx (M=16384,N=64->56,K=768), bf16 ----------------
__global__ __launch_bounds__(256, 2) void mm_x_bf16() {
    const int K = 768;
    int dir = blockIdx.z;
    __shared__ uint32_t As[128][17];
    __shared__ uint32_t Bs[16][72];
    int tid = threadIdx.x, lane = tid & 31, wid = tid >> 5;
    int wr = wid * 16;
    int g = lane >> 2, tg = lane & 3;
    const float* A = g_xc[dir] + (size_t)blockIdx.y * 128 * K;
    const uint32_t* Bp = g_wx_p[dir];
    float acc[8][4];
#pragma unroll
    for (int ni = 0; ni < 8; ni++)
#pragma unroll
        for (int q = 0; q < 4; q++) acc[ni][q] = 0.f;

    for (int k0 = 0; k0 < K; k0 += 32) {
#pragma unroll
        for (int i = 0; i < 4; i++) {
            int idx = tid + i * 256;
            int r = idx >> 3, f4 = idx & 7;
            float4 v = *(const float4*)(A + (size_t)r * K + k0 + f4 * 4);
            As[r][f4 * 2 + 0] = pack_bf2(v.x, v.y);
            As[r][f4 * 2 + 1] = pack_bf2(v.z, v.w);
        }
        {
            int kk = tid >> 4, n4 = (tid & 15) * 4;
            *(uint4*)&Bs[kk][n4] = *(const uint4*)(Bp + (size_t)(k0 / 2 + kk) * 64 + n4);
        }
        __syncthreads();
#pragma unroll
        for (int ks = 0; ks < 2; ks++) {
            int kb2 = ks * 8;
            uint32_t af[4], bf[8][2];
            af[0] = As[wr + g][kb2 + tg];
            af[1] = As[wr + g + 8][kb2 + tg];
            af[2] = As[wr + g][kb2 + tg + 4];
            af[3] = As[wr + g + 8][kb2 + tg + 4];
#pragma unroll
            for (int ni = 0; ni < 8; ni++) {
                bf[ni][0] = Bs[kb2 + tg][ni * 8 + g];
                bf[ni][1] = Bs[kb2 + tg + 4][ni * 8 + g];
            }
#pragma unroll
            for (int ni = 0; ni < 8; ni++) mma_bf16(acc[ni], af, bf[ni]);
        }
        __syncthreads();
    }
    size_t rbase = (size_t)blockIdx.y * 128;
#pragma unroll
    for (int ni = 0; ni < 8; ni++) {
        int c = ni * 8 + tg * 2;
        if (c < 56) {
            int r = wr + g;
            float* o0 = g_dbc[dir] + (rbase + r) * DBCW + c;
            float* o1 = g_dbc[dir] + (rbase + r + 8) * DBCW + c;
            o0[0] = acc[ni][0]; o0[1] = acc[ni][1];
            o1[0] = acc[ni][2]; o1[1] = acc[ni][3];
        }
    }
}

// ---------------- causal conv (rolling registers) + SiLU ----------------
__global__ __launch_bounds__(256) void conv_roll_kernel(const float* __restrict__ cw_f,
                                                        const float* __restrict__ cb_f,
                                                        const float* __restrict__ cw_b,
                                                        const float* __restrict__ cb_b) {
    int dir = blockIdx.z;
    int bb = blockIdx.y;
    int d = blockIdx.x * 256 + threadIdx.x;
    const float* cw = dir ? cw_b : cw_f;
    float w0 = cw[d * 4 + 0], w1 = cw[d * 4 + 1], w2 = cw[d * 4 + 2], w3 = cw[d * 4 + 3];
    float bias = (dir ? cb_b : cb_f)[d];
    const float* xz = g_xz + (size_t)bb * Ll * (2 * DI) + d;
    float* yo = g_xc[dir] + (size_t)bb * Ll * DI + d;
    float x1 = 0.f, x2 = 0.f, x3 = 0.f;
    for (int l = 0; l < Ll; l += 4) {
        float xv[4];
#pragma unroll
        for (int j = 0; j < 4; j++) {
            int lp = dir ? (Ll - 1 - (l + j)) : (l + j);
            xv[j] = xz[(size_t)lp * (2 * DI)];
        }
#pragma unroll
        for (int j = 0; j < 4; j++) {
            float a = bias + w3 * xv[j] + w2 * x1 + w1 * x2 + w0 * x3;
            x3 = x2; x2 = x1; x1 = xv[j];
            float s = a * (1.f / (1.f + __expf(-a)));
            yo[(size_t)(l + j) * DI] = s;
        }
    }
}

// ---------------- dt_proj + softplus ----------------
__global__ __launch_bounds__(256) void dtproj_kernel(const float* __restrict__ dtw_f,
                                                     const float* __restrict__ dtb_f,
                                                     const float* __restrict__ dtw_b,
                                                     const float* __restrict__ dtb_b) {
    int dir = blockIdx.z;
    int col = blockIdx.x * 256 + threadIdx.x;
    int r0 = blockIdx.y * 32;
    const float* Wd = dir ? dtw_b : dtw_f;
    float w[DTR];
#pragma unroll
    for (int k = 0; k < DTR; k++) w[k] = Wd[col * DTR + k];
    float bias = (dir ? dtb_b : dtb_f)[col];
    __shared__ float sdt[32 * DTR];
    for (int i = threadIdx.x; i < 32 * DTR; i += 256) {
        int rr = i / DTR, kk = i % DTR;
        sdt[i] = g_dbc[dir][(size_t)(r0 + rr) * DBCW + kk];
    }
    __syncthreads();
    for (int rr = 0; rr < 32; rr++) {
        float acc = bias;
#pragma unroll
        for (int k = 0; k < DTR; k++) acc += sdt[rr * DTR + k] * w[k];
        float sp = (acc > 20.f) ? acc : log1pf(__expf(acc));
        g_delta[dir][(size_t)(r0 + rr) * DI + col] = sp;
    }
}

// ---------------- scan pass 1: per-chunk local states (h0=0) + sum(dt) ----------------
__global__ __launch_bounds__(64) void scan_pass1(const float* __restrict__ Alog_f,
                                                 const float* __restrict__ Alog_b) {
    int dir = blockIdx.z;
    int bb = blockIdx.y >> 3, ch = blockIdx.y & 7;
    int d = blockIdx.x * 64 + threadIdx.x;
    int tb = ch * CHT;
    const float* Alog = dir ? Alog_b : Alog_f;
    const float* delta = g_delta[dir] + ((size_t)bb * Ll + tb) * DI + d;
    const float* u     = g_xc[dir]   + ((size_t)bb * Ll + tb) * DI + d;
    const float* dbc   = g_dbc[dir]  + ((size_t)bb * Ll + tb) * DBCW;

    float A[NS];
#pragma unroll
    for (int n = 0; n < NS; n++) A[n] = -__expf(Alog[d * NS + n]);
    bool fast = true;
#pragma unroll
    for (int n = 1; n < NS; n++)
        fast = fast && (fabsf(A[n] - (float)(n + 1) * A[0]) <= 1e-5f * fabsf(A[n]));

    __shared__ float sB[8][NS];
    float h[NS];
#pragma unroll
    for (int n = 0; n < NS; n++) h[n] = 0.f;
    float sdt = 0.f;

    for (int t0 = 0; t0 < CHT; t0 += 8) {
        float dl[8], ul[8], ql[8];
#pragma unroll
        for (int i = 0; i < 8; i++) {
            dl[i] = delta[(size_t)(t0 + i) * DI];
            ul[i] = u[(size_t)(t0 + i) * DI];
            ql[i] = __expf(dl[i] * A[0]);
        }
        __syncthreads();
        for (int i = threadIdx.x; i < 128; i += 64) {
            int tt = i >> 4, n = i & 15;
            sB[tt][n] = dbc[(size_t)(t0 + tt) * DBCW + DTR + n];
        }
        __syncthreads();
#pragma unroll
        for (int i = 0; i < 8; i++) {
            float dt = dl[i];
            float du = dt * ul[i];
            sdt += dt;
            if (fast) {
                float q = ql[i];
                float q2 = q * q, q4 = q2 * q2, q8 = q4 * q4;
                float q3 = q2 * q, q5 = q4 * q, q6 = q4 * q2, q7 = q4 * q3;
                float pw[NS] = {q, q2, q3, q4, q5, q6, q7, q8,
                                q8 * q, q8 * q2, q8 * q3, q8 * q4,
                                q8 * q5, q8 * q6, q8 * q7, q8 * q8};
#pragma unroll
                for (int n = 0; n < NS; n++) h[n] = h[n] * pw[n] + du * sB[i][n];
            } else {
#pragma unroll
                for (int n = 0; n < NS; n++) {
                    float dA = __expf(dt * A[n]);
                    h[n] = h[n] * dA + du * sB[i][n];
                }
            }
        }
    }
#pragma unroll
    for (int n = 0; n < NS; n++) g_hc[dir][bb][ch][n][d] = h[n];
    g_dts[dir][bb][ch][d] = sdt;
}

// ---------------- scan pass 2: combine chunk states -> entry states ----------------
__global__ __launch_bounds__(256) void scan_pass2(const float* __restrict__ Alog_f,
                                                  const float* __restrict__ Alog_b) {
    int gid = blockIdx.x * 256 + threadIdx.x;    // < 2*Bb*DI
    int dir = gid / (Bb * DI);
    int rem = gid % (Bb * DI);
    int bb = rem / DI, d = rem % DI;
    const float* Alog = dir ? Alog_b : Alog_f;
    float A[NS];
#pragma unroll
    for (int n = 0; n < NS; n++) A[n] = -__expf(Alog[d * NS + n]);
    float entry[NS];
#pragma unroll
    for (int n = 0; n < NS; n++) entry[n] = 0.f;
#pragma unroll
    for (int ch = 0; ch < NCH; ch++) {
        float S = g_dts[dir][bb][ch][d];
        float hl[NS];
#pragma unroll
        for (int n = 0; n < NS; n++) {
            hl[n] = g_hc[dir][bb][ch][n][d];
            g_hc[dir][bb][ch][n][d] = entry[n];
        }
#pragma unroll
        for (int n = 0; n < NS; n++)
            entry[n] = hl[n] + __expf(A[n] * S) * entry[n];
    }
}

// ---------------- scan pass 3: full scan per chunk from entry state ----------------
__global__ __launch_bounds__(64) void scan_pass3(const float* __restrict__ Alog_f,
                                                 const float* __restrict__ Alog_b,
                                                 const float* __restrict__ Dv_f,
                                                 const float* __restrict__ Dv_b) {
    int dir = blockIdx.z;
    int bb = blockIdx.y >> 3, ch = blockIdx.y & 7;
    int d = blockIdx.x * 64 + threadIdx.x;
    int tb = ch * CHT;
    const float* Alog = dir ? Alog_b : Alog_f;
    const float* Dvp  = dir ? Dv_b  : Dv_f;
    const float* delta = g_delta[dir] + ((size_t)bb * Ll + tb) * DI + d;
    const float* u     = g_xc[dir]   + ((size_t)bb * Ll + tb) * DI + d;
    const float* dbc   = g_dbc[dir]  + ((size_t)bb * Ll + tb) * DBCW;
    const float* zb    = g_xz + (size_t)bb * Ll * (2 * DI) + DI + d;
    float* yout        = g_y[dir] + (size_t)bb * Ll * DI + d;

    float A[NS];
#pragma unroll
    for (int n = 0; n < NS; n++) A[n] = -__expf(Alog[d * NS + n]);
    bool fast = true;
#pragma unroll
    for (int n = 1; n < NS; n++)
        fast = fast && (fabsf(A[n] - (float)(n + 1) * A[0]) <= 1e-5f * fabsf(A[n]));
    float Dv = Dvp[d];

    __shared__ float sB[8][NS], sC[8][NS];
    float h[NS];
#pragma unroll
    for (int n = 0; n < NS; n++) h[n] = g_hc[dir][bb][ch][n][d];

    for (int t0 = 0; t0 < CHT; t0 += 8) {
        float dl[8], ul[8], zl[8], ql[8];
#pragma unroll
        for (int i = 0; i < 8; i++) {
            dl[i] = delta[(size_t)(t0 + i) * DI];
            ul[i] = u[(size_t)(t0 + i) * DI];
            int t = tb + t0 + i;
            int op = dir ? (Ll - 1 - t) : t;
            zl[i] = zb[(size_t)op * (2 * DI)];
            ql[i] = __expf(dl[i] * A[0]);
        }
        __syncthreads();
        for (int i = threadIdx.x; i < 256; i += 64) {
            int which = i >> 7, tt = (i >> 4) & 7, n = i & 15;
            float v = dbc[(size_t)(t0 + tt) * DBCW + DTR + which * NS + n];
            if (which) sC[tt][n] = v; else sB[tt][n] = v;
        }
        __syncthreads();
#pragma unroll
        for (int i = 0; i < 8; i++) {
            float dt = dl[i];
            float du = dt * ul[i];
            float y = 0.f;
            if (fast) {
                float q = ql[i];
                float q2 = q * q, q4 = q2 * q2, q8 = q4 * q4;
                float q3 = q2 * q, q5 = q4 * q, q6 = q4 * q2, q7 = q4 * q3;
                float pw[NS] = {q, q2, q3, q4, q5, q6, q7, q8,
                                q8 * q, q8 * q2, q8 * q3, q8 * q4,
                                q8 * q5, q8 * q6, q8 * q7, q8 * q8};
#pragma unroll
                for (int n = 0; n < NS; n++) {
                    h[n] = h[n] * pw[n] + du * sB[i][n];
                    y += h[n] * sC[i][n];
                }
            } else {
#pragma unroll
                for (int n = 0; n < NS; n++) {
                    float dA = __expf(dt * A[n]);
                    h[n] = h[n] * dA + du * sB[i][n];
                    y += h[n] * sC[i][n];
                }
            }
            y += ul[i] * Dv;
            float z = zl[i];
            float sz = z * (1.f / (1.f + __expf(-z)));
            int t = tb + t0 + i;
            int op = dir ? (Ll - 1 - t) : t;
            yout[(size_t)op * DI] = y * sz;
        }
    }
}

// ---------------- launch ----------------
extern "C" void kernel_launch(void* const* d_in, const int* in_sizes, int n_in,
                              void* d_out, int out_size) {
    const float* x        = (const float*)d_in[0];
    const float* ln_w     = (const float*)d_in[1];
    const float* ln_b     = (const float*)d_in[2];
    const float* in_proj  = (const float*)d_in[3];
    const float* out_proj = (const float*)d_in[4];
    const float* cw_f     = (const float*)d_in[5];
    const float* cb_f     = (const float*)d_in[6];
    const float* xw_f     = (const float*)d_in[7];
    const float* dtw_f    = (const float*)d_in[8];
    const float* dtb_f    = (const float*)d_in[9];
    const float* Alog_f   = (const float*)d_in[10];
    const float* Dv_f     = (const float*)d_in[11];
    const float* cw_b     = (const float*)d_in[12];
    const float* cb_b     = (const float*)d_in[13];
    const float* xw_b     = (const float*)d_in[14];
    const float* dtw_b    = (const float*)d_in[15];
    const float* dtb_b    = (const float*)d_in[16];
    const float* Alog_b   = (const float*)d_in[17];
    const float* Dv_b     = (const float*)d_in[18];
    float* out = (float*)d_out;

    ln_kernel<<<BLr, 384>>>(x, ln_w, ln_b);
    transpose_in<<<(192 * 1536 + 255) / 256, 256>>>(in_proj);
    transpose_out<<<(384 * 384 + 255) / 256, 256>>>(out_proj);
    transpose_x<<<(384 * 64 + 255) / 256, 256>>>(xw_f, xw_b);
    mm_in_bf16<<<dim3(12, 128), 256>>>();
    conv_roll_kernel<<<dim3(3, Bb, 2), 256>>>(cw_f, cb_f, cw_b, cb_b);
    mm_x_bf16<<<dim3(1, 128, 2), 256>>>();
    dtproj_kernel<<<dim3(3, BLr / 32, 2), 256>>>(dtw_f, dtb_f, dtw_b, dtb_b);
    scan_pass1<<<dim3(12, 128, 2), 64>>>(Alog_f, Alog_b);
    scan_pass2<<<(2 * Bb * DI) / 256, 256>>>(Alog_f, Alog_b);
    scan_pass3<<<dim3(12, 128, 2), 64>>>(Alog_f, Alog_b, Dv_f, Dv_b);
    mm_out_bf16<<<dim3(3, 128), 256>>>(x, out);
}

// round 6
// speedup vs baseline: 3.2750x; 1.1313x over previous
#include <cuda_runtime.h>
#include <cuda_bf16.h>
#include <cstdint>

#define Bb   16
#define Ll   1024
#define DM   384
#define DI   768
#define NS   16
#define DTR  24
#define DBCW 56            // DTR + 2*NS
#define BLr  16384         // Bb*Ll
#define NCH  8             // scan chunks
#define CHT  128           // steps per chunk

// ---------------- scratch (device globals; no allocations) ----------------
__device__ __nv_bfloat16 g_xnb[(size_t)BLr * DM];        // ln out, bf16
__device__ uint32_t g_win_p[(size_t)(DM / 2) * 1536];    // bf16x2 pairs along k
__device__ uint32_t g_wout_p[(size_t)(DI / 2) * DM];
__device__ uint32_t g_wx_p[2][(size_t)(DI / 2) * 64];
__device__ __nv_bfloat16 g_xh[(size_t)BLr * DI];         // x-half of in_proj, bf16
__device__ float         g_z[(size_t)BLr * DI];          // z-half, fp32 (precision)
__device__ __nv_bfloat16 g_xc[2][(size_t)BLr * DI];      // conv+silu out, bf16
__device__ float         g_dbc[2][(size_t)BLr * DBCW];
__device__ __nv_bfloat16 g_delta[2][(size_t)BLr * DI];
__device__ __nv_bfloat16 g_y[2][(size_t)BLr * DI];       // y*silu(z), bf16
__device__ float g_hc[2][Bb][NCH][NS][DI];
__device__ float g_dts[2][Bb][NCH][DI];

// ---------------- bf16 helpers ----------------
__device__ __forceinline__ uint32_t pack_bf2(float lo, float hi) {
    uint32_t r; asm("cvt.rn.bf16x2.f32 %0, %1, %2;" : "=r"(r) : "f"(hi), "f"(lo)); return r;
}
__device__ __forceinline__ uint32_t add_bf2(uint32_t a, uint32_t b) {
    float alo = __uint_as_float(a << 16), ahi = __uint_as_float(a & 0xffff0000u);
    float blo = __uint_as_float(b << 16), bhi = __uint_as_float(b & 0xffff0000u);
    return pack_bf2(alo + blo, ahi + bhi);
}
__device__ __forceinline__ void mma_bf16(float (&d)[4], const uint32_t (&a)[4], const uint32_t (&b)[2]) {
    asm volatile("mma.sync.aligned.m16n8k16.row.col.f32.bf16.bf16.f32 "
                 "{%0,%1,%2,%3}, {%4,%5,%6,%7}, {%8,%9}, {%0,%1,%2,%3};"
                 : "+f"(d[0]), "+f"(d[1]), "+f"(d[2]), "+f"(d[3])
                 : "r"(a[0]), "r"(a[1]), "r"(a[2]), "r"(a[3]), "r"(b[0]), "r"(b[1]));
}

// ---------------- LayerNorm (bf16 out) ----------------
__global__ __launch_bounds__(384) void ln_kernel(const float* __restrict__ x,
                                                 const float* __restrict__ w,
                                                 const float* __restrict__ b) {
    int r = blockIdx.x, t = threadIdx.x;
    float v = x[(size_t)r * DM + t];
    float s = v, s2 = v * v;
#pragma unroll
    for (int o = 16; o; o >>= 1) {
        s  += __shfl_xor_sync(0xffffffffu, s, o);
        s2 += __shfl_xor_sync(0xffffffffu, s2, o);
    }
    __shared__ float ps[12], ps2[12];
    __shared__ float smu, srstd;
    if ((t & 31) == 0) { ps[t >> 5] = s; ps2[t >> 5] = s2; }
    __syncthreads();
    if (t == 0) {
        float a = 0.f, a2 = 0.f;
#pragma unroll
        for (int i = 0; i < 12; i++) { a += ps[i]; a2 += ps2[i]; }
        float mu = a / DM;
        float var = a2 / DM - mu * mu;
        smu = mu; srstd = rsqrtf(var + 1e-5f);
    }
    __syncthreads();
    g_xnb[(size_t)r * DM + t] = __float2bfloat16((v - smu) * srstd * w[t] + b[t]);
}

// ---------------- weight transposes + bf16 packing ----------------
__global__ void transpose_in(const float* __restrict__ W) {
    int i = blockIdx.x * 256 + threadIdx.x;
    if (i < 192 * 1536) {
        int k2 = i / 1536, n = i % 1536;
        float2 v = *(const float2*)(W + (size_t)n * 384 + 2 * k2);
        g_win_p[i] = pack_bf2(v.x, v.y);
    }
}
__global__ void transpose_out(const float* __restrict__ W) {
    int i = blockIdx.x * 256 + threadIdx.x;
    if (i < 384 * 384) {
        int k2 = i / 384, n = i % 384;
        float2 v = *(const float2*)(W + (size_t)n * 768 + 2 * k2);
        g_wout_p[i] = pack_bf2(v.x, v.y);
    }
}
__global__ void transpose_x(const float* __restrict__ Wf, const float* __restrict__ Wb) {
    int i = blockIdx.x * 256 + threadIdx.x;
    if (i < 384 * 64) {
        int k2 = i / 64, n = i % 64;
        if (n < 56) {
            float2 vf = *(const float2*)(Wf + (size_t)n * 768 + 2 * k2);
            float2 vb = *(const float2*)(Wb + (size_t)n * 768 + 2 * k2);
            g_wx_p[0][i] = pack_bf2(vf.x, vf.y);
            g_wx_p[1][i] = pack_bf2(vb.x, vb.y);
        } else {
            g_wx_p[0][i] = 0u; g_wx_p[1][i] = 0u;
        }
    }
}

// ---------------- mm_in: [xh|z] = xn @ Win  (M=16384,N=1536,K=384), bf16 ----------------
__global__ __launch_bounds__(256, 2) void mm_in_bf16() {
    const int K = 384, N = 1536;
    __shared__ uint32_t As[128][20];
    __shared__ uint32_t Bs[16][136];
    int tid = threadIdx.x, lane = tid & 31, wid = tid >> 5;
    int wr = (wid & 3) * 32, wc = (wid >> 2) * 64;
    int g = lane >> 2, tg = lane & 3;
    const uint32_t* Ap = (const uint32_t*)g_xnb + (size_t)blockIdx.y * 128 * (K / 2);
    const uint32_t* Bp = g_win_p + blockIdx.x * 128;
    float acc[2][8][4];
#pragma unroll
    for (int mi = 0; mi < 2; mi++)
#pragma unroll
        for (int ni = 0; ni < 8; ni++)
#pragma unroll
            for (int q = 0; q < 4; q++) acc[mi][ni][q] = 0.f;

    for (int k0 = 0; k0 < K; k0 += 32) {
#pragma unroll
        for (int i = 0; i < 2; i++) {
            int idx = tid + i * 256;
            int r = idx >> 2, q4 = (idx & 3) * 4;
            *(uint4*)&As[r][q4] = *(const uint4*)(Ap + (size_t)r * (K / 2) + k0 / 2 + q4);
        }
#pragma unroll
        for (int i = 0; i < 2; i++) {
            int idx = tid + i * 256;
            int kk = idx >> 5, n4 = (idx & 31) * 4;
            *(uint4*)&Bs[kk][n4] = *(const uint4*)(Bp + (size_t)(k0 / 2 + kk) * N + n4);
        }
        __syncthreads();
#pragma unroll
        for (int ks = 0; ks < 2; ks++) {
            int kb2 = ks * 8;
            uint32_t af[2][4], bf[8][2];
#pragma unroll
            for (int mi = 0; mi < 2; mi++) {
                int r0 = wr + mi * 16;
                af[mi][0] = As[r0 + g][kb2 + tg];
                af[mi][1] = As[r0 + g + 8][kb2 + tg];
                af[mi][2] = As[r0 + g][kb2 + tg + 4];
                af[mi][3] = As[r0 + g + 8][kb2 + tg + 4];
            }
#pragma unroll
            for (int ni = 0; ni < 8; ni++) {
                bf[ni][0] = Bs[kb2 + tg][wc + ni * 8 + g];
                bf[ni][1] = Bs[kb2 + tg + 4][wc + ni * 8 + g];
            }
#pragma unroll
            for (int mi = 0; mi < 2; mi++)
#pragma unroll
                for (int ni = 0; ni < 8; ni++) mma_bf16(acc[mi][ni], af[mi], bf[ni]);
        }
        __syncthreads();
    }
    size_t rbase = (size_t)blockIdx.y * 128;
    if (blockIdx.x < 6) {
        // x-half -> bf16 g_xh, col base blockIdx.x*128
        uint32_t* C = (uint32_t*)g_xh;
        int cb = blockIdx.x * 128;
#pragma unroll
        for (int mi = 0; mi < 2; mi++)
#pragma unroll
            for (int ni = 0; ni < 8; ni++) {
                int r = wr + mi * 16 + g, c = cb + wc + ni * 8 + tg * 2;
                C[((rbase + r) * DI + c) >> 1]     = pack_bf2(acc[mi][ni][0], acc[mi][ni][1]);
                C[((rbase + r + 8) * DI + c) >> 1] = pack_bf2(acc[mi][ni][2], acc[mi][ni][3]);
            }
    } else {
        // z-half -> fp32 g_z, col base (blockIdx.x-6)*128
        int cb = (blockIdx.x - 6) * 128;
#pragma unroll
        for (int mi = 0; mi < 2; mi++)
#pragma unroll
            for (int ni = 0; ni < 8; ni++) {
                int r = wr + mi * 16 + g, c = cb + wc + ni * 8 + tg * 2;
                *(float2*)(g_z + (rbase + r) * DI + c)     = make_float2(acc[mi][ni][0], acc[mi][ni][1]);
                *(float2*)(g_z + (rbase + r + 8) * DI + c) = make_float2(acc[mi][ni][2], acc[mi][ni][3]);
            }
    }
}

// ---------------- mm_out: out = x + (yf+yr) @ Wout (M=16384,N=384,K=768), bf16 ----------------
__global__ __launch_bounds__(256, 2) void mm_out_bf16(const float* __restrict__ xres,
                                                      float* __restrict__ out) {
    const int K = 768, N = 384;
    __shared__ uint32_t As[128][20];
    __shared__ uint32_t Bs[16][136];
    int tid = threadIdx.x, lane = tid & 31, wid = tid >> 5;
    int wr = (wid & 3) * 32, wc = (wid >> 2) * 64;
    int g = lane >> 2, tg = lane & 3;
    const uint32_t* A0 = (const uint32_t*)g_y[0] + (size_t)blockIdx.y * 128 * (K / 2);
    const uint32_t* A1 = (const uint32_t*)g_y[1] + (size_t)blockIdx.y * 128 * (K / 2);
    const uint32_t* Bp = g_wout_p + blockIdx.x * 128;
    float acc[2][8][4];
#pragma unroll
    for (int mi = 0; mi < 2; mi++)
#pragma unroll
        for (int ni = 0; ni < 8; ni++)
#pragma unroll
            for (int q = 0; q < 4; q++) acc[mi][ni][q] = 0.f;

    for (int k0 = 0; k0 < K; k0 += 32) {
#pragma unroll
        for (int i = 0; i < 2; i++) {
            int idx = tid + i * 256;
            int r = idx >> 2, q4 = (idx & 3) * 4;
            uint4 v0 = *(const uint4*)(A0 + (size_t)r * (K / 2) + k0 / 2 + q4);
            uint4 v1 = *(const uint4*)(A1 + (size_t)r * (K / 2) + k0 / 2 + q4);
            As[r][q4 + 0] = add_bf2(v0.x, v1.x);
            As[r][q4 + 1] = add_bf2(v0.y, v1.y);
            As[r][q4 + 2] = add_bf2(v0.z, v1.z);
            As[r][q4 + 3] = add_bf2(v0.w, v1.w);
        }
#pragma unroll
        for (int i = 0; i < 2; i++) {
            int idx = tid + i * 256;
            int kk = idx >> 5, n4 = (idx & 31) * 4;
            *(uint4*)&Bs[kk][n4] = *(const uint4*)(Bp + (size_t)(k0 / 2 + kk) * N + n4);
        }
        __syncthreads();
#pragma unroll
        for (int ks = 0; ks < 2; ks++) {
            int kb2 = ks * 8;
            uint32_t af[2][4], bf[8][2];
#pragma unroll
            for (int mi = 0; mi < 2; mi++) {
                int r0 = wr + mi * 16;
                af[mi][0] = As[r0 + g][kb2 + tg];
                af[mi][1] = As[r0 + g + 8][kb2 + tg];
                af[mi][2] = As[r0 + g][kb2 + tg + 4];
                af[mi][3] = As[r0 + g + 8][kb2 + tg + 4];
            }
#pragma unroll
            for (int ni = 0; ni < 8; ni++) {
                bf[ni][0] = Bs[kb2 + tg][wc + ni * 8 + g];
                bf[ni][1] = Bs[kb2 + tg + 4][wc + ni * 8 + g];
            }
#pragma unroll
            for (int mi = 0; mi < 2; mi++)
#pragma unroll
                for (int ni = 0; ni < 8; ni++) mma_bf16(acc[mi][ni], af[mi], bf[ni]);
        }
        __syncthreads();
    }
    size_t rbase = (size_t)blockIdx.y * 128;
    int cbase = blockIdx.x * 128;
#pragma unroll
    for (int mi = 0; mi < 2; mi++)
#pragma unroll
        for (int ni = 0; ni < 8; ni++) {
            int r = wr + mi * 16 + g, c = wc + ni * 8 + tg * 2;
            size_t o0 = (rbase + r) * N + cbase + c;
            size_t o1 = (rbase + r + 8) * N + cbase + c;
            out[o0]     = acc[mi][ni][0] + xres[o0];
            out[o0 + 1] = acc[mi][ni][1] + xres[o0 + 1];
            out[o1]     = acc[mi][ni][2] + xres[o1];
            out[o1 + 1] = acc[mi][ni][3] + xres[o1 + 1];
        }
}

// ---------------- mm_x: dbc = xc @ Wx (M=16384,N=64->56,K=768), bf16 ----------------
__global__ __launch_bounds__(256, 2) void mm_x_bf16() {
    const int K = 768;
    int dir = blockIdx.z;
    __shared__ uint32_t As[128][20];
    __shared__ uint32_t Bs[16][72];
    int tid = threadIdx.x, lane = tid & 31, wid = tid >> 5;
    int wr = wid * 16;
    int g = lane >> 2, tg = lane & 3;
    const uint32_t* Ap = (const uint32_t*)g_xc[dir] + (size_t)blockIdx.y * 128 * (K / 2);
    const uint32_t* Bp = g_wx_p[dir];
    float acc[8][4];
#pragma unroll
    for (int ni = 0; ni < 8; ni++)
#pragma unroll
        for (int q = 0; q < 4; q++) acc[ni][q] = 0.f;

    for (int k0 = 0; k0 < K; k0 += 32) {
#pragma unroll
        for (int i = 0; i < 2; i++) {
            int idx = tid + i * 256;
            int r = idx >> 2, q4 = (idx & 3) * 4;
            *(uint4*)&As[r][q4] = *(const uint4*)(Ap + (size_t)r * (K / 2) + k0 / 2 + q4);
        }
        {
            int kk = tid >> 4, n4 = (tid & 15) * 4;
            *(uint4*)&Bs[kk][n4] = *(const uint4*)(Bp + (size_t)(k0 / 2 + kk) * 64 + n4);
        }
        __syncthreads();
#pragma unroll
        for (int ks = 0; ks < 2; ks++) {
            int kb2 = ks * 8;
            uint32_t af[4], bf[8][2];
            af[0] = As[wr + g][kb2 + tg];
            af[1] = As[wr + g + 8][kb2 + tg];
            af[2] = As[wr + g][kb2 + tg + 4];
            af[3] = As[wr + g + 8][kb2 + tg + 4];
#pragma unroll
            for (int ni = 0; ni < 8; ni++) {
                bf[ni][0] = Bs[kb2 + tg][ni * 8 + g];
                bf[ni][1] = Bs[kb2 + tg + 4][ni * 8 + g];
            }
#pragma unroll
            for (int ni = 0; ni < 8; ni++) mma_bf16(acc[ni], af, bf[ni]);
        }
        __syncthreads();
    }
    size_t rbase = (size_t)blockIdx.y * 128;
#pragma unroll
    for (int ni = 0; ni < 8; ni++) {
        int c = ni * 8 + tg * 2;
        if (c < 56) {
            int r = wr + g;
            float* o0 = g_dbc[dir] + (rbase + r) * DBCW + c;
            float* o1 = g_dbc[dir] + (rbase + r + 8) * DBCW + c;
            o0[0] = acc[ni][0]; o0[1] = acc[ni][1];
            o1[0] = acc[ni][2]; o1[1] = acc[ni][3];
        }
    }
}

// ---------------- causal conv (rolling registers) + SiLU, bf16 in/out ----------------
__global__ __launch_bounds__(256) void conv_roll_kernel(const float* __restrict__ cw_f,
                                                        const float* __restrict__ cb_f,
                                                        const float* __restrict__ cw_b,
                                                        const float* __restrict__ cb_b) {
    int dir = blockIdx.z;
    int bb = blockIdx.y;
    int d = blockIdx.x * 256 + threadIdx.x;
    const float* cw = dir ? cw_b : cw_f;
    float w0 = cw[d * 4 + 0], w1 = cw[d * 4 + 1], w2 = cw[d * 4 + 2], w3 = cw[d * 4 + 3];
    float bias = (dir ? cb_b : cb_f)[d];
    const __nv_bfloat16* xh = g_xh + (size_t)bb * Ll * DI + d;
    __nv_bfloat16* yo = g_xc[dir] + (size_t)bb * Ll * DI + d;
    float x1 = 0.f, x2 = 0.f, x3 = 0.f;
    for (int l = 0; l < Ll; l += 4) {
        float xv[4];
#pragma unroll
        for (int j = 0; j < 4; j++) {
            int lp = dir ? (Ll - 1 - (l + j)) : (l + j);
            xv[j] = __bfloat162float(xh[(size_t)lp * DI]);
        }
#pragma unroll
        for (int j = 0; j < 4; j++) {
            float a = bias + w3 * xv[j] + w2 * x1 + w1 * x2 + w0 * x3;
            x3 = x2; x2 = x1; x1 = xv[j];
            float s = a * (1.f / (1.f + __expf(-a)));
            yo[(size_t)(l + j) * DI] = __float2bfloat16(s);
        }
    }
}

// ---------------- dt_proj + softplus (bf16 out) ----------------
__global__ __launch_bounds__(256) void dtproj_kernel(const float* __restrict__ dtw_f,
                                                     const float* __restrict__ dtb_f,
                                                     const float* __restrict__ dtw_b,
                                                     const float* __restrict__ dtb_b) {
    int dir = blockIdx.z;
    int col = blockIdx.x * 256 + threadIdx.x;
    int r0 = blockIdx.y * 32;
    const float* Wd = dir ? dtw_b : dtw_f;
    float w[DTR];
#pragma unroll
    for (int k = 0; k < DTR; k++) w[k] = Wd[col * DTR + k];
    float bias = (dir ? dtb_b : dtb_f)[col];
    __shared__ float sdt[32 * DTR];
    for (int i = threadIdx.x; i < 32 * DTR; i += 256) {
        int rr = i / DTR, kk = i % DTR;
        sdt[i] = g_dbc[dir][(size_t)(r0 + rr) * DBCW + kk];
    }
    __syncthreads();
    for (int rr = 0; rr < 32; rr++) {
        float acc = bias;
#pragma unroll
        for (int k = 0; k < DTR; k++) acc += sdt[rr * DTR + k] * w[k];
        float sp = (acc > 20.f) ? acc : log1pf(__expf(acc));
        g_delta[dir][(size_t)(r0 + rr) * DI + col] = __float2bfloat16(sp);
    }
}

// ---------------- scan pass 1: per-chunk local states (h0=0) + sum(dt) ----------------
__global__ __launch_bounds__(64) void scan_pass1(const float* __restrict__ Alog_f,
                                                 const float* __restrict__ Alog_b) {
    int dir = blockIdx.z;
    int bb = blockIdx.y >> 3, ch = blockIdx.y & 7;
    int d = blockIdx.x * 64 + threadIdx.x;
    int tb = ch * CHT;
    const float* Alog = dir ? Alog_b : Alog_f;
    const __nv_bfloat16* delta = g_delta[dir] + ((size_t)bb * Ll + tb) * DI + d;
    const __nv_bfloat16* u     = g_xc[dir]   + ((size_t)bb * Ll + tb) * DI + d;
    const float* dbc           = g_dbc[dir]  + ((size_t)bb * Ll + tb) * DBCW;

    float A[NS];
#pragma unroll
    for (int n = 0; n < NS; n++) A[n] = -__expf(Alog[d * NS + n]);
    bool fast = true;
#pragma unroll
    for (int n = 1; n < NS; n++)
        fast = fast && (fabsf(A[n] - (float)(n + 1) * A[0]) <= 1e-5f * fabsf(A[n]));

    __shared__ float sB[8][NS];
    float h[NS];
#pragma unroll
    for (int n = 0; n < NS; n++) h[n] = 0.f;
    float sdt = 0.f;

    for (int t0 = 0; t0 < CHT; t0 += 8) {
        float dl[8], ul[8], ql[8];
#pragma unroll
        for (int i = 0; i < 8; i++) {
            dl[i] = __bfloat162float(delta[(size_t)(t0 + i) * DI]);
            ul[i] = __bfloat162float(u[(size_t)(t0 + i) * DI]);
            ql[i] = __expf(dl[i] * A[0]);
        }
        __syncthreads();
        for (int i = threadIdx.x; i < 128; i += 64) {
            int tt = i >> 4, n = i & 15;
            sB[tt][n] = dbc[(size_t)(t0 + tt) * DBCW + DTR + n];
        }
        __syncthreads();
#pragma unroll
        for (int i = 0; i < 8; i++) {
            float dt = dl[i];
            float du = dt * ul[i];
            sdt += dt;
            if (fast) {
                float q = ql[i];
                float q2 = q * q, q4 = q2 * q2, q8 = q4 * q4;
                float q3 = q2 * q, q5 = q4 * q, q6 = q4 * q2, q7 = q4 * q3;
                float pw[NS] = {q, q2, q3, q4, q5, q6, q7, q8,
                                q8 * q, q8 * q2, q8 * q3, q8 * q4,
                                q8 * q5, q8 * q6, q8 * q7, q8 * q8};
#pragma unroll
                for (int n = 0; n < NS; n++) h[n] = h[n] * pw[n] + du * sB[i][n];
            } else {
#pragma unroll
                for (int n = 0; n < NS; n++) {
                    float dA = __expf(dt * A[n]);
                    h[n] = h[n] * dA + du * sB[i][n];
                }
            }
        }
    }
#pragma unroll
    for (int n = 0; n < NS; n++) g_hc[dir][bb][ch][n][d] = h[n];
    g_dts[dir][bb][ch][d] = sdt;
}

// ---------------- scan pass 2: combine chunk states -> entry states ----------------
__global__ __launch_bounds__(256) void scan_pass2(const float* __restrict__ Alog_f,
                                                  const float* __restrict__ Alog_b) {
    int gid = blockIdx.x * 256 + threadIdx.x;
    int dir = gid / (Bb * DI);
    int rem = gid % (Bb * DI);
    int bb = rem / DI, d = rem % DI;
    const float* Alog = dir ? Alog_b : Alog_f;
    float A[NS];
#pragma unroll
    for (int n = 0; n < NS; n++) A[n] = -__expf(Alog[d * NS + n]);
    float entry[NS];
#pragma unroll
    for (int n = 0; n < NS; n++) entry[n] = 0.f;
#pragma unroll
    for (int ch = 0; ch < NCH; ch++) {
        float S = g_dts[dir][bb][ch][d];
        float hl[NS];
#pragma unroll
        for (int n = 0; n < NS; n++) {
            hl[n] = g_hc[dir][bb][ch][n][d];
            g_hc[dir][bb][ch][n][d] = entry[n];
        }
#pragma unroll
        for (int n = 0; n < NS; n++)
            entry[n] = hl[n] + __expf(A[n] * S) * entry[n];
    }
}

// ---------------- scan pass 3: full scan per chunk from entry state ----------------
__global__ __launch_bounds__(64) void scan_pass3(const float* __restrict__ Alog_f,
                                                 const float* __restrict__ Alog_b,
                                                 const float* __restrict__ Dv_f,
                                                 const float* __restrict__ Dv_b) {
    int dir = blockIdx.z;
    int bb = blockIdx.y >> 3, ch = blockIdx.y & 7;
    int d = blockIdx.x * 64 + threadIdx.x;
    int tb = ch * CHT;
    const float* Alog = dir ? Alog_b : Alog_f;
    const float* Dvp  = dir ? Dv_b  : Dv_f;
    const __nv_bfloat16* delta = g_delta[dir] + ((size_t)bb * Ll + tb) * DI + d;
    const __nv_bfloat16* u     = g_xc[dir]   + ((size_t)bb * Ll + tb) * DI + d;
    const float* dbc           = g_dbc[dir]  + ((size_t)bb * Ll + tb) * DBCW;
    const float* zb            = g_z + (size_t)bb * Ll * DI + d;
    __nv_bfloat16* yout        = g_y[dir] + (size_t)bb * Ll * DI + d;

    float A[NS];
#pragma unroll
    for (int n = 0; n < NS; n++) A[n] = -__expf(Alog[d * NS + n]);
    bool fast = true;
#pragma unroll
    for (int n = 1; n < NS; n++)
        fast = fast && (fabsf(A[n] - (float)(n + 1) * A[0]) <= 1e-5f * fabsf(A[n]));
    float Dv = Dvp[d];

    __shared__ float sB[8][NS], sC[8][NS];
    float h[NS];
#pragma unroll
    for (int n = 0; n < NS; n++) h[n] = g_hc[dir][bb][ch][n][d];

    for (int t0 = 0; t0 < CHT; t0 += 8) {
        float dl[8], ul[8], zl[8], ql[8];
#pragma unroll
        for (int i = 0; i < 8; i++) {
            dl[i] = __bfloat162float(delta[(size_t)(t0 + i) * DI]);
            ul[i] = __bfloat162float(u[(size_t)(t0 + i) * DI]);
            int t = tb + t0 + i;
            int op = dir ? (Ll - 1 - t) : t;
            zl[i] = zb[(size_t)op * DI];
            ql[i] = __expf(dl[i] * A[0]);
        }
        __syncthreads();
        for (int i = threadIdx.x; i < 256; i += 64) {
            int which = i >> 7, tt = (i >> 4) & 7, n = i & 15;
            float v = dbc[(size_t)(t0 + tt) * DBCW + DTR + which * NS + n];
            if (which) sC[tt][n] = v; else sB[tt][n] = v;
        }
        __syncthreads();
#pragma unroll
        for (int i = 0; i < 8; i++) {
            float dt = dl[i];
            float du = dt * ul[i];
            float y = 0.f;
            if (fast) {
                float q = ql[i];
                float q2 = q * q, q4 = q2 * q2, q8 = q4 * q4;
                float q3 = q2 * q, q5 = q4 * q, q6 = q4 * q2, q7 = q4 * q3;
                float pw[NS] = {q, q2, q3, q4, q5, q6, q7, q8,
                                q8 * q, q8 * q2, q8 * q3, q8 * q4,
                                q8 * q5, q8 * q6, q8 * q7, q8 * q8};
#pragma unroll
                for (int n = 0; n < NS; n++) {
                    h[n] = h[n] * pw[n] + du * sB[i][n];
                    y += h[n] * sC[i][n];
                }
            } else {
#pragma unroll
                for (int n = 0; n < NS; n++) {
                    float dA = __expf(dt * A[n]);
                    h[n] = h[n] * dA + du * sB[i][n];
                    y += h[n] * sC[i][n];
                }
            }
            y += ul[i] * Dv;
            float z = zl[i];
            float sz = z * (1.f / (1.f + __expf(-z)));
            int t = tb + t0 + i;
            int op = dir ? (Ll - 1 - t) : t;
            yout[(size_t)op * DI] = __float2bfloat16(y * sz);
        }
    }
}

// ---------------- launch ----------------
extern "C" void kernel_launch(void* const* d_in, const int* in_sizes, int n_in,
                              void* d_out, int out_size) {
    const float* x        = (const float*)d_in[0];
    const float* ln_w     = (const float*)d_in[1];
    const float* ln_b     = (const float*)d_in[2];
    const float* in_proj  = (const float*)d_in[3];
    const float* out_proj = (const float*)d_in[4];
    const float* cw_f     = (const float*)d_in[5];
    const float* cb_f     = (const float*)d_in[6];
    const float* xw_f     = (const float*)d_in[7];
    const float* dtw_f    = (const float*)d_in[8];
    const float* dtb_f    = (const float*)d_in[9];
    const float* Alog_f   = (const float*)d_in[10];
    const float* Dv_f     = (const float*)d_in[11];
    const float* cw_b     = (const float*)d_in[12];
    const float* cb_b     = (const float*)d_in[13];
    const float* xw_b     = (const float*)d_in[14];
    const float* dtw_b    = (const float*)d_in[15];
    const float* dtb_b    = (const float*)d_in[16];
    const float* Alog_b   = (const float*)d_in[17];
    const float* Dv_b     = (const float*)d_in[18];
    float* out = (float*)d_out;

    ln_kernel<<<BLr, 384>>>(x, ln_w, ln_b);
    transpose_in<<<(192 * 1536 + 255) / 256, 256>>>(in_proj);
    transpose_out<<<(384 * 384 + 255) / 256, 256>>>(out_proj);
    transpose_x<<<(384 * 64 + 255) / 256, 256>>>(xw_f, xw_b);
    mm_in_bf16<<<dim3(12, 128), 256>>>();
    conv_roll_kernel<<<dim3(3, Bb, 2), 256>>>(cw_f, cb_f, cw_b, cb_b);
    mm_x_bf16<<<dim3(1, 128, 2), 256>>>();
    dtproj_kernel<<<dim3(3, BLr / 32, 2), 256>>>(dtw_f, dtb_f, dtw_b, dtb_b);
    scan_pass1<<<dim3(12, 128, 2), 64>>>(Alog_f, Alog_b);
    scan_pass2<<<(2 * Bb * DI) / 256, 256>>>(Alog_f, Alog_b);
    scan_pass3<<<dim3(12, 128, 2), 64>>>(Alog_f, Alog_b, Dv_f, Dv_b);
    mm_out_bf16<<<dim3(3, 128), 256>>>(x, out);
}

// round 7
// speedup vs baseline: 3.5349x; 1.0793x over previous
#include <cuda_runtime.h>
#include <cuda_bf16.h>
#include <cstdint>

#define Bb   16
#define Ll   1024
#define DM   384
#define DI   768
#define NS   16
#define DTR  24
#define DBCW 56            // DTR + 2*NS
#define BLr  16384         // Bb*Ll
#define NCH  8             // scan chunks
#define CHT  128           // steps per chunk

// ---------------- scratch (device globals; no allocations) ----------------
__device__ __nv_bfloat16 g_xnb[(size_t)BLr * DM];
__device__ uint32_t g_win_p[(size_t)(DM / 2) * 1536];
__device__ uint32_t g_wout_p[(size_t)(DI / 2) * DM];
__device__ uint32_t g_wx_p[2][(size_t)(DI / 2) * 64];
__device__ __nv_bfloat16 g_xh[(size_t)BLr * DI];
__device__ float         g_z[(size_t)BLr * DI];
__device__ __nv_bfloat16 g_xc[2][(size_t)BLr * DI];
__device__ float         g_dbc[2][(size_t)BLr * DBCW];
__device__ __nv_bfloat16 g_delta[2][(size_t)BLr * DI];
__device__ __nv_bfloat16 g_y[2][(size_t)BLr * DI];
__device__ __nv_bfloat16 g_ysum[(size_t)BLr * DI];
__device__ float g_hc[2][Bb][NCH][NS][DI];
__device__ float g_dts[2][Bb][NCH][DI];

// ---------------- bf16 helpers ----------------
__device__ __forceinline__ uint32_t pack_bf2(float lo, float hi) {
    uint32_t r; asm("cvt.rn.bf16x2.f32 %0, %1, %2;" : "=r"(r) : "f"(hi), "f"(lo)); return r;
}
__device__ __forceinline__ uint32_t add_bf2(uint32_t a, uint32_t b) {
    float alo = __uint_as_float(a << 16), ahi = __uint_as_float(a & 0xffff0000u);
    float blo = __uint_as_float(b << 16), bhi = __uint_as_float(b & 0xffff0000u);
    return pack_bf2(alo + blo, ahi + bhi);
}
__device__ __forceinline__ void mma_bf16(float (&d)[4], const uint32_t (&a)[4], const uint32_t (&b)[2]) {
    asm volatile("mma.sync.aligned.m16n8k16.row.col.f32.bf16.bf16.f32 "
                 "{%0,%1,%2,%3}, {%4,%5,%6,%7}, {%8,%9}, {%0,%1,%2,%3};"
                 : "+f"(d[0]), "+f"(d[1]), "+f"(d[2]), "+f"(d[3])
                 : "r"(a[0]), "r"(a[1]), "r"(a[2]), "r"(a[3]), "r"(b[0]), "r"(b[1]));
}

// ---------------- LayerNorm (bf16 out) ----------------
__global__ __launch_bounds__(384) void ln_kernel(const float* __restrict__ x,
                                                 const float* __restrict__ w,
                                                 const float* __restrict__ b) {
    int r = blockIdx.x, t = threadIdx.x;
    float v = x[(size_t)r * DM + t];
    float s = v, s2 = v * v;
#pragma unroll
    for (int o = 16; o; o >>= 1) {
        s  += __shfl_xor_sync(0xffffffffu, s, o);
        s2 += __shfl_xor_sync(0xffffffffu, s2, o);
    }
    __shared__ float ps[12], ps2[12];
    __shared__ float smu, srstd;
    if ((t & 31) == 0) { ps[t >> 5] = s; ps2[t >> 5] = s2; }
    __syncthreads();
    if (t == 0) {
        float a = 0.f, a2 = 0.f;
#pragma unroll
        for (int i = 0; i < 12; i++) { a += ps[i]; a2 += ps2[i]; }
        float mu = a / DM;
        float var = a2 / DM - mu * mu;
        smu = mu; srstd = rsqrtf(var + 1e-5f);
    }
    __syncthreads();
    g_xnb[(size_t)r * DM + t] = __float2bfloat16((v - smu) * srstd * w[t] + b[t]);
}

// ---------------- weight transposes + bf16 packing ----------------
__global__ void transpose_in(const float* __restrict__ W) {
    int i = blockIdx.x * 256 + threadIdx.x;
    if (i < 192 * 1536) {
        int k2 = i / 1536, n = i % 1536;
        float2 v = *(const float2*)(W + (size_t)n * 384 + 2 * k2);
        g_win_p[i] = pack_bf2(v.x, v.y);
    }
}
__global__ void transpose_out(const float* __restrict__ W) {
    int i = blockIdx.x * 256 + threadIdx.x;
    if (i < 384 * 384) {
        int k2 = i / 384, n = i % 384;
        float2 v = *(const float2*)(W + (size_t)n * 768 + 2 * k2);
        g_wout_p[i] = pack_bf2(v.x, v.y);
    }
}
__global__ void transpose_x(const float* __restrict__ Wf, const float* __restrict__ Wb) {
    int i = blockIdx.x * 256 + threadIdx.x;
    if (i < 384 * 64) {
        int k2 = i / 64, n = i % 64;
        if (n < 56) {
            float2 vf = *(const float2*)(Wf + (size_t)n * 768 + 2 * k2);
            float2 vb = *(const float2*)(Wb + (size_t)n * 768 + 2 * k2);
            g_wx_p[0][i] = pack_bf2(vf.x, vf.y);
            g_wx_p[1][i] = pack_bf2(vb.x, vb.y);
        } else {
            g_wx_p[0][i] = 0u; g_wx_p[1][i] = 0u;
        }
    }
}

// ---------------- mm_in: [xh|z] = xn @ Win  (M=16384,N=1536,K=384), pipelined ----------------
__global__ __launch_bounds__(256, 2) void mm_in_bf16() {
    const int K = 384, N = 1536;
    __shared__ uint32_t As[128][20];
    __shared__ uint32_t Bs[16][136];
    int tid = threadIdx.x, lane = tid & 31, wid = tid >> 5;
    int wr = (wid & 3) * 32, wc = (wid >> 2) * 64;
    int g = lane >> 2, tg = lane & 3;
    const uint32_t* Ap = (const uint32_t*)g_xnb + (size_t)blockIdx.y * 128 * (K / 2);
    const uint32_t* Bp = g_win_p + blockIdx.x * 128;
    float acc[2][8][4] = {};

    int ar0 = tid >> 2, ar1 = (tid + 256) >> 2, ac = (tid & 3) * 4;
    int bk0 = tid >> 5, bk1 = (tid + 256) >> 5, bn = (tid & 31) * 4;
    uint4 ra0, ra1, rb0, rb1;
    ra0 = *(const uint4*)(Ap + (size_t)ar0 * (K / 2) + ac);
    ra1 = *(const uint4*)(Ap + (size_t)ar1 * (K / 2) + ac);
    rb0 = *(const uint4*)(Bp + (size_t)bk0 * N + bn);
    rb1 = *(const uint4*)(Bp + (size_t)bk1 * N + bn);

    for (int k0 = 0; k0 < K; k0 += 32) {
        *(uint4*)&As[ar0][ac] = ra0;
        *(uint4*)&As[ar1][ac] = ra1;
        *(uint4*)&Bs[bk0][bn] = rb0;
        *(uint4*)&Bs[bk1][bn] = rb1;
        __syncthreads();
        if (k0 + 32 < K) {
            int kh = (k0 + 32) / 2;
            ra0 = *(const uint4*)(Ap + (size_t)ar0 * (K / 2) + kh + ac);
            ra1 = *(const uint4*)(Ap + (size_t)ar1 * (K / 2) + kh + ac);
            rb0 = *(const uint4*)(Bp + (size_t)(kh + bk0) * N + bn);
            rb1 = *(const uint4*)(Bp + (size_t)(kh + bk1) * N + bn);
        }
#pragma unroll
        for (int ks = 0; ks < 2; ks++) {
            int kb2 = ks * 8;
            uint32_t af[2][4], bf[8][2];
#pragma unroll
            for (int mi = 0; mi < 2; mi++) {
                int r0 = wr + mi * 16;
                af[mi][0] = As[r0 + g][kb2 + tg];
                af[mi][1] = As[r0 + g + 8][kb2 + tg];
                af[mi][2] = As[r0 + g][kb2 + tg + 4];
                af[mi][3] = As[r0 + g + 8][kb2 + tg + 4];
            }
#pragma unroll
            for (int ni = 0; ni < 8; ni++) {
                bf[ni][0] = Bs[kb2 + tg][wc + ni * 8 + g];
                bf[ni][1] = Bs[kb2 + tg + 4][wc + ni * 8 + g];
            }
#pragma unroll
            for (int mi = 0; mi < 2; mi++)
#pragma unroll
                for (int ni = 0; ni < 8; ni++) mma_bf16(acc[mi][ni], af[mi], bf[ni]);
        }
        __syncthreads();
    }
    size_t rbase = (size_t)blockIdx.y * 128;
    if (blockIdx.x < 6) {
        uint32_t* C = (uint32_t*)g_xh;
        int cb = blockIdx.x * 128;
#pragma unroll
        for (int mi = 0; mi < 2; mi++)
#pragma unroll
            for (int ni = 0; ni < 8; ni++) {
                int r = wr + mi * 16 + g, c = cb + wc + ni * 8 + tg * 2;
                C[((rbase + r) * DI + c) >> 1]     = pack_bf2(acc[mi][ni][0], acc[mi][ni][1]);
                C[((rbase + r + 8) * DI + c) >> 1] = pack_bf2(acc[mi][ni][2], acc[mi][ni][3]);
            }
    } else {
        int cb = (blockIdx.x - 6) * 128;
#pragma unroll
        for (int mi = 0; mi < 2; mi++)
#pragma unroll
            for (int ni = 0; ni < 8; ni++) {
                int r = wr + mi * 16 + g, c = cb + wc + ni * 8 + tg * 2;
                *(float2*)(g_z + (rbase + r) * DI + c)     = make_float2(acc[mi][ni][0], acc[mi][ni][1]);
                *(float2*)(g_z + (rbase + r + 8) * DI + c) = make_float2(acc[mi][ni][2], acc[mi][ni][3]);
            }
    }
}

// ---------------- ysum = yf + yr (bf16) ----------------
__global__ __launch_bounds__(256) void ysum_kernel() {
    size_t i = (size_t)blockIdx.x * 256 + threadIdx.x;   // uint4 index
    const uint4* a = (const uint4*)g_y[0];
    const uint4* b = (const uint4*)g_y[1];
    uint4 va = a[i], vb = b[i], o;
    o.x = add_bf2(va.x, vb.x); o.y = add_bf2(va.y, vb.y);
    o.z = add_bf2(va.z, vb.z); o.w = add_bf2(va.w, vb.w);
    ((uint4*)g_ysum)[i] = o;
}

// ---------------- mm_out: out = x + ysum @ Wout (M=16384,N=384,K=768), pipelined ----------------
__global__ __launch_bounds__(256, 2) void mm_out_bf16(const float* __restrict__ xres,
                                                      float* __restrict__ out) {
    const int K = 768, N = 384;
    __shared__ uint32_t As[128][20];
    __shared__ uint32_t Bs[16][136];
    int tid = threadIdx.x, lane = tid & 31, wid = tid >> 5;
    int wr = (wid & 3) * 32, wc = (wid >> 2) * 64;
    int g = lane >> 2, tg = lane & 3;
    const uint32_t* Ap = (const uint32_t*)g_ysum + (size_t)blockIdx.y * 128 * (K / 2);
    const uint32_t* Bp = g_wout_p + blockIdx.x * 128;
    float acc[2][8][4] = {};

    int ar0 = tid >> 2, ar1 = (tid + 256) >> 2, ac = (tid & 3) * 4;
    int bk0 = tid >> 5, bk1 = (tid + 256) >> 5, bn = (tid & 31) * 4;
    uint4 ra0, ra1, rb0, rb1;
    ra0 = *(const uint4*)(Ap + (size_t)ar0 * (K / 2) + ac);
    ra1 = *(const uint4*)(Ap + (size_t)ar1 * (K / 2) + ac);
    rb0 = *(const uint4*)(Bp + (size_t)bk0 * N + bn);
    rb1 = *(const uint4*)(Bp + (size_t)bk1 * N + bn);

    for (int k0 = 0; k0 < K; k0 += 32) {
        *(uint4*)&As[ar0][ac] = ra0;
        *(uint4*)&As[ar1][ac] = ra1;
        *(uint4*)&Bs[bk0][bn] = rb0;
        *(uint4*)&Bs[bk1][bn] = rb1;
        __syncthreads();
        if (k0 + 32 < K) {
            int kh = (k0 + 32) / 2;
            ra0 = *(const uint4*)(Ap + (size_t)ar0 * (K / 2) + kh + ac);
            ra1 = *(const uint4*)(Ap + (size_t)ar1 * (K / 2) + kh + ac);
            rb0 = *(const uint4*)(Bp + (size_t)(kh + bk0) * N + bn);
            rb1 = *(const uint4*)(Bp + (size_t)(kh + bk1) * N + bn);
        }
#pragma unroll
        for (int ks = 0; ks < 2; ks++) {
            int kb2 = ks * 8;
            uint32_t af[2][4], bf[8][2];
#pragma unroll
            for (int mi = 0; mi < 2; mi++) {
                int r0 = wr + mi * 16;
                af[mi][0] = As[r0 + g][kb2 + tg];
                af[mi][1] = As[r0 + g + 8][kb2 + tg];
                af[mi][2] = As[r0 + g][kb2 + tg + 4];
                af[mi][3] = As[r0 + g + 8][kb2 + tg + 4];
            }
#pragma unroll
            for (int ni = 0; ni < 8; ni++) {
                bf[ni][0] = Bs[kb2 + tg][wc + ni * 8 + g];
                bf[ni][1] = Bs[kb2 + tg + 4][wc + ni * 8 + g];
            }
#pragma unroll
            for (int mi = 0; mi < 2; mi++)
#pragma unroll
                for (int ni = 0; ni < 8; ni++) mma_bf16(acc[mi][ni], af[mi], bf[ni]);
        }
        __syncthreads();
    }
    size_t rbase = (size_t)blockIdx.y * 128;
    int cbase = blockIdx.x * 128;
#pragma unroll
    for (int mi = 0; mi < 2; mi++)
#pragma unroll
        for (int ni = 0; ni < 8; ni++) {
            int r = wr + mi * 16 + g, c = wc + ni * 8 + tg * 2;
            size_t o0 = (rbase + r) * N + cbase + c;
            size_t o1 = (rbase + r + 8) * N + cbase + c;
            out[o0]     = acc[mi][ni][0] + xres[o0];
            out[o0 + 1] = acc[mi][ni][1] + xres[o0 + 1];
            out[o1]     = acc[mi][ni][2] + xres[o1];
            out[o1 + 1] = acc[mi][ni][3] + xres[o1 + 1];
        }
}

// ---------------- mm_x: dbc = xc @ Wx (M=16384,N=64->56,K=768), pipelined ----------------
__global__ __launch_bounds__(256, 2) void mm_x_bf16() {
    const int K = 768;
    int dir = blockIdx.z;
    __shared__ uint32_t As[128][20];
    __shared__ uint32_t Bs[16][72];
    int tid = threadIdx.x, lane = tid & 31, wid = tid >> 5;
    int wr = wid * 16;
    int g = lane >> 2, tg = lane & 3;
    const uint32_t* Ap = (const uint32_t*)g_xc[dir] + (size_t)blockIdx.y * 128 * (K / 2);
    const uint32_t* Bp = g_wx_p[dir];
    float acc[8][4] = {};

    int ar0 = tid >> 2, ar1 = (tid + 256) >> 2, ac = (tid & 3) * 4;
    int bk = tid >> 4, bn = (tid & 15) * 4;
    uint4 ra0, ra1, rb;
    ra0 = *(const uint4*)(Ap + (size_t)ar0 * (K / 2) + ac);
    ra1 = *(const uint4*)(Ap + (size_t)ar1 * (K / 2) + ac);
    rb  = *(const uint4*)(Bp + (size_t)bk * 64 + bn);

    for (int k0 = 0; k0 < K; k0 += 32) {
        *(uint4*)&As[ar0][ac] = ra0;
        *(uint4*)&As[ar1][ac] = ra1;
        *(uint4*)&Bs[bk][bn] = rb;
        __syncthreads();
        if (k0 + 32 < K) {
            int kh = (k0 + 32) / 2;
            ra0 = *(const uint4*)(Ap + (size_t)ar0 * (K / 2) + kh + ac);
            ra1 = *(const uint4*)(Ap + (size_t)ar1 * (K / 2) + kh + ac);
            rb  = *(const uint4*)(Bp + (size_t)(kh + bk) * 64 + bn);
        }
#pragma unroll
        for (int ks = 0; ks < 2; ks++) {
            int kb2 = ks * 8;
            uint32_t af[4], bf[8][2];
            af[0] = As[wr + g][kb2 + tg];
            af[1] = As[wr + g + 8][kb2 + tg];
            af[2] = As[wr + g][kb2 + tg + 4];
            af[3] = As[wr + g + 8][kb2 + tg + 4];
#pragma unroll
            for (int ni = 0; ni < 8; ni++) {
                bf[ni][0] = Bs[kb2 + tg][ni * 8 + g];
                bf[ni][1] = Bs[kb2 + tg + 4][ni * 8 + g];
            }
#pragma unroll
            for (int ni = 0; ni < 8; ni++) mma_bf16(acc[ni], af, bf[ni]);
        }
        __syncthreads();
    }
    size_t rbase = (size_t)blockIdx.y * 128;
#pragma unroll
    for (int ni = 0; ni < 8; ni++) {
        int c = ni * 8 + tg * 2;
        if (c < 56) {
            int r = wr + g;
            float* o0 = g_dbc[dir] + (rbase + r) * DBCW + c;
            float* o1 = g_dbc[dir] + (rbase + r + 8) * DBCW + c;
            o0[0] = acc[ni][0]; o0[1] = acc[ni][1];
            o1[0] = acc[ni][2]; o1[1] = acc[ni][3];
        }
    }
}

// ---------------- causal conv (rolling registers) + SiLU ----------------
__global__ __launch_bounds__(256) void conv_roll_kernel(const float* __restrict__ cw_f,
                                                        const float* __restrict__ cb_f,
                                                        const float* __restrict__ cw_b,
                                                        const float* __restrict__ cb_b) {
    int dir = blockIdx.z;
    int bb = blockIdx.y;
    int d = blockIdx.x * 256 + threadIdx.x;
    const float* cw = dir ? cw_b : cw_f;
    float w0 = cw[d * 4 + 0], w1 = cw[d * 4 + 1], w2 = cw[d * 4 + 2], w3 = cw[d * 4 + 3];
    float bias = (dir ? cb_b : cb_f)[d];
    const __nv_bfloat16* xh = g_xh + (size_t)bb * Ll * DI + d;
    __nv_bfloat16* yo = g_xc[dir] + (size_t)bb * Ll * DI + d;
    float x1 = 0.f, x2 = 0.f, x3 = 0.f;
    for (int l = 0; l < Ll; l += 4) {
        float xv[4];
#pragma unroll
        for (int j = 0; j < 4; j++) {
            int lp = dir ? (Ll - 1 - (l + j)) : (l + j);
            xv[j] = __bfloat162float(xh[(size_t)lp * DI]);
        }
#pragma unroll
        for (int j = 0; j < 4; j++) {
            float a = bias + w3 * xv[j] + w2 * x1 + w1 * x2 + w0 * x3;
            x3 = x2; x2 = x1; x1 = xv[j];
            float s = a * (1.f / (1.f + __expf(-a)));
            yo[(size_t)(l + j) * DI] = __float2bfloat16(s);
        }
    }
}

// ---------------- dt_proj + softplus (float4 smem) ----------------
__global__ __launch_bounds__(256) void dtproj_kernel(const float* __restrict__ dtw_f,
                                                     const float* __restrict__ dtb_f,
                                                     const float* __restrict__ dtw_b,
                                                     const float* __restrict__ dtb_b) {
    int dir = blockIdx.z;
    int col = blockIdx.x * 256 + threadIdx.x;
    int r0 = blockIdx.y * 32;
    const float* Wd = dir ? dtw_b : dtw_f;
    float4 w[6];
#pragma unroll
    for (int j = 0; j < 6; j++) w[j] = *(const float4*)(Wd + col * DTR + j * 4);
    float bias = (dir ? dtb_b : dtb_f)[col];
    __shared__ __align__(16) float sdt[32 * DTR];
    if (threadIdx.x < 192) {
        int rr = threadIdx.x / 6, j = threadIdx.x % 6;
        *(float4*)&sdt[rr * DTR + j * 4] =
            *(const float4*)(g_dbc[dir] + (size_t)(r0 + rr) * DBCW + j * 4);
    }
    __syncthreads();
    for (int rr = 0; rr < 32; rr++) {
        float acc = bias;
#pragma unroll
        for (int j = 0; j < 6; j++) {
            float4 v = *(const float4*)&sdt[rr * DTR + j * 4];
            acc += v.x * w[j].x + v.y * w[j].y + v.z * w[j].z + v.w * w[j].w;
        }
        float sp = (acc > 20.f) ? acc : log1pf(__expf(acc));
        g_delta[dir][(size_t)(r0 + rr) * DI + col] = __float2bfloat16(sp);
    }
}

// ---------------- scan pass 1: per-chunk local states (h0=0) + sum(dt) ----------------
__global__ __launch_bounds__(64) void scan_pass1(const float* __restrict__ Alog_f,
                                                 const float* __restrict__ Alog_b) {
    int dir = blockIdx.z;
    int bb = blockIdx.y >> 3, ch = blockIdx.y & 7;
    int d = blockIdx.x * 64 + threadIdx.x;
    int tb = ch * CHT;
    const float* Alog = dir ? Alog_b : Alog_f;
    const __nv_bfloat16* delta = g_delta[dir] + ((size_t)bb * Ll + tb) * DI + d;
    const __nv_bfloat16* u     = g_xc[dir]   + ((size_t)bb * Ll + tb) * DI + d;
    const float* dbc           = g_dbc[dir]  + ((size_t)bb * Ll + tb) * DBCW;

    float A[NS];
#pragma unroll
    for (int n = 0; n < NS; n++) A[n] = -__expf(Alog[d * NS + n]);
    bool fast = true;
#pragma unroll
    for (int n = 1; n < NS; n++)
        fast = fast && (fabsf(A[n] - (float)(n + 1) * A[0]) <= 1e-5f * fabsf(A[n]));

    __shared__ float4 sB4[8][4];
    float h[NS];
#pragma unroll
    for (int n = 0; n < NS; n++) h[n] = 0.f;
    float sdt = 0.f;

    for (int t0 = 0; t0 < CHT; t0 += 8) {
        float dl[8], ul[8], ql[8];
#pragma unroll
        for (int i = 0; i < 8; i++) {
            dl[i] = __bfloat162float(delta[(size_t)(t0 + i) * DI]);
            ul[i] = __bfloat162float(u[(size_t)(t0 + i) * DI]);
            ql[i] = __expf(dl[i] * A[0]);
        }
        __syncthreads();
        if (threadIdx.x < 32) {
            int tt = threadIdx.x >> 2, j = threadIdx.x & 3;
            sB4[tt][j] = *(const float4*)(dbc + (size_t)(t0 + tt) * DBCW + DTR + j * 4);
        }
        __syncthreads();
#pragma unroll
        for (int i = 0; i < 8; i++) {
            float4 b0 = sB4[i][0], b1 = sB4[i][1], b2 = sB4[i][2], b3 = sB4[i][3];
            float Bv[NS] = {b0.x, b0.y, b0.z, b0.w, b1.x, b1.y, b1.z, b1.w,
                            b2.x, b2.y, b2.z, b2.w, b3.x, b3.y, b3.z, b3.w};
            float dt = dl[i];
            float du = dt * ul[i];
            sdt += dt;
            if (fast) {
                float q = ql[i];
                float q2 = q * q, q4 = q2 * q2, q8 = q4 * q4;
                float q3 = q2 * q, q5 = q4 * q, q6 = q4 * q2, q7 = q4 * q3;
                float pw[NS] = {q, q2, q3, q4, q5, q6, q7, q8,
                                q8 * q, q8 * q2, q8 * q3, q8 * q4,
                                q8 * q5, q8 * q6, q8 * q7, q8 * q8};
#pragma unroll
                for (int n = 0; n < NS; n++) h[n] = h[n] * pw[n] + du * Bv[n];
            } else {
#pragma unroll
                for (int n = 0; n < NS; n++) {
                    float dA = __expf(dt * A[n]);
                    h[n] = h[n] * dA + du * Bv[n];
                }
            }
        }
    }
#pragma unroll
    for (int n = 0; n < NS; n++) g_hc[dir][bb][ch][n][d] = h[n];
    g_dts[dir][bb][ch][d] = sdt;
}

// ---------------- scan pass 2: combine chunk states -> entry states ----------------
__global__ __launch_bounds__(256) void scan_pass2(const float* __restrict__ Alog_f,
                                                  const float* __restrict__ Alog_b) {
    int gid = blockIdx.x * 256 + threadIdx.x;
    int dir = gid / (Bb * DI);
    int rem = gid % (Bb * DI);
    int bb = rem / DI, d = rem % DI;
    const float* Alog = dir ? Alog_b : Alog_f;
    float A[NS];
#pragma unroll
    for (int n = 0; n < NS; n++) A[n] = -__expf(Alog[d * NS + n]);
    float entry[NS];
#pragma unroll
    for (int n = 0; n < NS; n++) entry[n] = 0.f;
#pragma unroll
    for (int ch = 0; ch < NCH; ch++) {
        float S = g_dts[dir][bb][ch][d];
        float hl[NS];
#pragma unroll
        for (int n = 0; n < NS; n++) {
            hl[n] = g_hc[dir][bb][ch][n][d];
            g_hc[dir][bb][ch][n][d] = entry[n];
        }
#pragma unroll
        for (int n = 0; n < NS; n++)
            entry[n] = hl[n] + __expf(A[n] * S) * entry[n];
    }
}

// ---------------- scan pass 3: full scan per chunk from entry state ----------------
__global__ __launch_bounds__(64) void scan_pass3(const float* __restrict__ Alog_f,
                                                 const float* __restrict__ Alog_b,
                                                 const float* __restrict__ Dv_f,
                                                 const float* __restrict__ Dv_b) {
    int dir = blockIdx.z;
    int bb = blockIdx.y >> 3, ch = blockIdx.y & 7;
    int d = blockIdx.x * 64 + threadIdx.x;
    int tb = ch * CHT;
    const float* Alog = dir ? Alog_b : Alog_f;
    const float* Dvp  = dir ? Dv_b  : Dv_f;
    const __nv_bfloat16* delta = g_delta[dir] + ((size_t)bb * Ll + tb) * DI + d;
    const __nv_bfloat16* u     = g_xc[dir]   + ((size_t)bb * Ll + tb) * DI + d;
    const float* dbc           = g_dbc[dir]  + ((size_t)bb * Ll + tb) * DBCW;
    const float* zb            = g_z + (size_t)bb * Ll * DI + d;
    __nv_bfloat16* yout        = g_y[dir] + (size_t)bb * Ll * DI + d;

    float A[NS];
#pragma unroll
    for (int n = 0; n < NS; n++) A[n] = -__expf(Alog[d * NS + n]);
    bool fast = true;
#pragma unroll
    for (int n = 1; n < NS; n++)
        fast = fast && (fabsf(A[n] - (float)(n + 1) * A[0]) <= 1e-5f * fabsf(A[n]));
    float Dv = Dvp[d];

    __shared__ float4 sBC[8][8];   // [t][0..3]=B, [4..7]=C
    float h[NS];
#pragma unroll
    for (int n = 0; n < NS; n++) h[n] = g_hc[dir][bb][ch][n][d];

    for (int t0 = 0; t0 < CHT; t0 += 8) {
        float dl[8], ul[8], zl[8], ql[8];
#pragma unroll
        for (int i = 0; i < 8; i++) {
            dl[i] = __bfloat162float(delta[(size_t)(t0 + i) * DI]);
            ul[i] = __bfloat162float(u[(size_t)(t0 + i) * DI]);
            int t = tb + t0 + i;
            int op = dir ? (Ll - 1 - t) : t;
            zl[i] = zb[(size_t)op * DI];
            ql[i] = __expf(dl[i] * A[0]);
        }
        __syncthreads();
        {
            int tt = threadIdx.x >> 3, j = threadIdx.x & 7;
            sBC[tt][j] = *(const float4*)(dbc + (size_t)(t0 + tt) * DBCW + DTR + j * 4);
        }
        __syncthreads();
#pragma unroll
        for (int i = 0; i < 8; i++) {
            float4 b0 = sBC[i][0], b1 = sBC[i][1], b2 = sBC[i][2], b3 = sBC[i][3];
            float4 c0 = sBC[i][4], c1 = sBC[i][5], c2 = sBC[i][6], c3 = sBC[i][7];
            float Bv[NS] = {b0.x, b0.y, b0.z, b0.w, b1.x, b1.y, b1.z, b1.w,
                            b2.x, b2.y, b2.z, b2.w, b3.x, b3.y, b3.z, b3.w};
            float Cv[NS] = {c0.x, c0.y, c0.z, c0.w, c1.x, c1.y, c1.z, c1.w,
                            c2.x, c2.y, c2.z, c2.w, c3.x, c3.y, c3.z, c3.w};
            float dt = dl[i];
            float du = dt * ul[i];
            float y = 0.f;
            if (fast) {
                float q = ql[i];
                float q2 = q * q, q4 = q2 * q2, q8 = q4 * q4;
                float q3 = q2 * q, q5 = q4 * q, q6 = q4 * q2, q7 = q4 * q3;
                float pw[NS] = {q, q2, q3, q4, q5, q6, q7, q8,
                                q8 * q, q8 * q2, q8 * q3, q8 * q4,
                                q8 * q5, q8 * q6, q8 * q7, q8 * q8};
#pragma unroll
                for (int n = 0; n < NS; n++) {
                    h[n] = h[n] * pw[n] + du * Bv[n];
                    y += h[n] * Cv[n];
                }
            } else {
#pragma unroll
                for (int n = 0; n < NS; n++) {
                    float dA = __expf(dt * A[n]);
                    h[n] = h[n] * dA + du * Bv[n];
                    y += h[n] * Cv[n];
                }
            }
            y += ul[i] * Dv;
            float z = zl[i];
            float sz = z * (1.f / (1.f + __expf(-z)));
            int t = tb + t0 + i;
            int op = dir ? (Ll - 1 - t) : t;
            yout[(size_t)op * DI] = __float2bfloat16(y * sz);
        }
    }
}

// ---------------- launch ----------------
extern "C" void kernel_launch(void* const* d_in, const int* in_sizes, int n_in,
                              void* d_out, int out_size) {
    const float* x        = (const float*)d_in[0];
    const float* ln_w     = (const float*)d_in[1];
    const float* ln_b     = (const float*)d_in[2];
    const float* in_proj  = (const float*)d_in[3];
    const float* out_proj = (const float*)d_in[4];
    const float* cw_f     = (const float*)d_in[5];
    const float* cb_f     = (const float*)d_in[6];
    const float* xw_f     = (const float*)d_in[7];
    const float* dtw_f    = (const float*)d_in[8];
    const float* dtb_f    = (const float*)d_in[9];
    const float* Alog_f   = (const float*)d_in[10];
    const float* Dv_f     = (const float*)d_in[11];
    const float* cw_b     = (const float*)d_in[12];
    const float* cb_b     = (const float*)d_in[13];
    const float* xw_b     = (const float*)d_in[14];
    const float* dtw_b    = (const float*)d_in[15];
    const float* dtb_b    = (const float*)d_in[16];
    const float* Alog_b   = (const float*)d_in[17];
    const float* Dv_b     = (const float*)d_in[18];
    float* out = (float*)d_out;

    ln_kernel<<<BLr, 384>>>(x, ln_w, ln_b);
    transpose_in<<<(192 * 1536 + 255) / 256, 256>>>(in_proj);
    transpose_out<<<(384 * 384 + 255) / 256, 256>>>(out_proj);
    transpose_x<<<(384 * 64 + 255) / 256, 256>>>(xw_f, xw_b);
    mm_in_bf16<<<dim3(12, 128), 256>>>();
    conv_roll_kernel<<<dim3(3, Bb, 2), 256>>>(cw_f, cb_f, cw_b, cb_b);
    mm_x_bf16<<<dim3(1, 128, 2), 256>>>();
    dtproj_kernel<<<dim3(3, BLr / 32, 2), 256>>>(dtw_f, dtb_f, dtw_b, dtb_b);
    scan_pass1<<<dim3(12, 128, 2), 64>>>(Alog_f, Alog_b);
    scan_pass2<<<(2 * Bb * DI) / 256, 256>>>(Alog_f, Alog_b);
    scan_pass3<<<dim3(12, 128, 2), 64>>>(Alog_f, Alog_b, Dv_f, Dv_b);
    ysum_kernel<<<(BLr * DI / 8) / 256, 256>>>();
    mm_out_bf16<<<dim3(3, 128), 256>>>(x, out);
}

// round 9
// speedup vs baseline: 4.5243x; 1.2799x over previous
#include <cuda_runtime.h>
#include <cuda_bf16.h>
#include <cstdint>

#define Bb   16
#define Ll   1024
#define DM   384
#define DI   768
#define NS   16
#define DTR  24
#define DBCW 56            // DTR + 2*NS
#define BLr  16384         // Bb*Ll
#define NCH  8             // scan chunks
#define CHT  128           // steps per chunk

// ---------------- scratch (device globals; no allocations) ----------------
__device__ __nv_bfloat16 g_xnb[(size_t)BLr * DM];
__device__ uint32_t g_win_p[(size_t)(DM / 2) * 1536];
__device__ uint32_t g_wout_p[(size_t)(DI / 2) * DM];
__device__ uint32_t g_wx_p[2][(size_t)(DI / 2) * 64];
__device__ __nv_bfloat16 g_xh[(size_t)BLr * DI];
__device__ float         g_z[(size_t)BLr * DI];
__device__ __nv_bfloat16 g_xc[2][(size_t)BLr * DI];
__device__ float         g_dbc[2][(size_t)BLr * DBCW];
__device__ __nv_bfloat16 g_delta[2][(size_t)BLr * DI];
__device__ __nv_bfloat16 g_y[2][(size_t)BLr * DI];
__device__ float g_hc[2][Bb][NCH][NS][DI];
__device__ float g_dts[2][Bb][NCH][DI];

// ---------------- bf16 helpers ----------------
__device__ __forceinline__ uint32_t pack_bf2(float lo, float hi) {
    uint32_t r; asm("cvt.rn.bf16x2.f32 %0, %1, %2;" : "=r"(r) : "f"(hi), "f"(lo)); return r;
}
__device__ __forceinline__ uint32_t hadd2_bf2(uint32_t a, uint32_t b) {
    __nv_bfloat162 r = __hadd2(*(__nv_bfloat162*)&a, *(__nv_bfloat162*)&b);
    return *(uint32_t*)&r;
}
__device__ __forceinline__ void mma_bf16(float (&d)[4], const uint32_t (&a)[4], const uint32_t (&b)[2]) {
    asm volatile("mma.sync.aligned.m16n8k16.row.col.f32.bf16.bf16.f32 "
                 "{%0,%1,%2,%3}, {%4,%5,%6,%7}, {%8,%9}, {%0,%1,%2,%3};"
                 : "+f"(d[0]), "+f"(d[1]), "+f"(d[2]), "+f"(d[3])
                 : "r"(a[0]), "r"(a[1]), "r"(a[2]), "r"(a[3]), "r"(b[0]), "r"(b[1]));
}

// ---------------- LayerNorm (bf16 out) ----------------
__global__ __launch_bounds__(384) void ln_kernel(const float* __restrict__ x,
                                                 const float* __restrict__ w,
                                                 const float* __restrict__ b) {
    int r = blockIdx.x, t = threadIdx.x;
    float v = x[(size_t)r * DM + t];
    float s = v, s2 = v * v;
#pragma unroll
    for (int o = 16; o; o >>= 1) {
        s  += __shfl_xor_sync(0xffffffffu, s, o);
        s2 += __shfl_xor_sync(0xffffffffu, s2, o);
    }
    __shared__ float ps[12], ps2[12];
    __shared__ float smu, srstd;
    if ((t & 31) == 0) { ps[t >> 5] = s; ps2[t >> 5] = s2; }
    __syncthreads();
    if (t == 0) {
        float a = 0.f, a2 = 0.f;
#pragma unroll
        for (int i = 0; i < 12; i++) { a += ps[i]; a2 += ps2[i]; }
        float mu = a / DM;
        float var = a2 / DM - mu * mu;
        smu = mu; srstd = rsqrtf(var + 1e-5f);
    }
    __syncthreads();
    g_xnb[(size_t)r * DM + t] = __float2bfloat16((v - smu) * srstd * w[t] + b[t]);
}

// ---------------- fused weight transposes + bf16 packing ----------------
#define TIN  (192 * 1536)
#define TOUT (384 * 384)
#define TX   (384 * 64)
__global__ void transpose_all(const float* __restrict__ Win, const float* __restrict__ Wout,
                              const float* __restrict__ Wxf, const float* __restrict__ Wxb) {
    int i = blockIdx.x * 256 + threadIdx.x;
    if (i < TIN) {
        int k2 = i / 1536, n = i % 1536;
        float2 v = *(const float2*)(Win + (size_t)n * 384 + 2 * k2);
        g_win_p[i] = pack_bf2(v.x, v.y);
    } else if (i < TIN + TOUT) {
        int j = i - TIN;
        int k2 = j / 384, n = j % 384;
        float2 v = *(const float2*)(Wout + (size_t)n * 768 + 2 * k2);
        g_wout_p[j] = pack_bf2(v.x, v.y);
    } else if (i < TIN + TOUT + TX) {
        int j = i - TIN - TOUT;
        int k2 = j / 64, n = j % 64;
        if (n < 56) {
            float2 vf = *(const float2*)(Wxf + (size_t)n * 768 + 2 * k2);
            float2 vb = *(const float2*)(Wxb + (size_t)n * 768 + 2 * k2);
            g_wx_p[0][j] = pack_bf2(vf.x, vf.y);
            g_wx_p[1][j] = pack_bf2(vb.x, vb.y);
        } else {
            g_wx_p[0][j] = 0u; g_wx_p[1][j] = 0u;
        }
    }
}

// ---------------- mm_in: [xh|z] = xn @ Win  (M=16384,N=1536,K=384), pipelined ----------------
__global__ __launch_bounds__(256, 2) void mm_in_bf16() {
    const int K = 384, N = 1536;
    __shared__ uint32_t As[128][20];
    __shared__ uint32_t Bs[16][136];
    int tid = threadIdx.x, lane = tid & 31, wid = tid >> 5;
    int wr = (wid & 3) * 32, wc = (wid >> 2) * 64;
    int g = lane >> 2, tg = lane & 3;
    const uint32_t* Ap = (const uint32_t*)g_xnb + (size_t)blockIdx.y * 128 * (K / 2);
    const uint32_t* Bp = g_win_p + blockIdx.x * 128;
    float acc[2][8][4] = {};

    int ar0 = tid >> 2, ar1 = (tid + 256) >> 2, ac = (tid & 3) * 4;
    int bk0 = tid >> 5, bk1 = (tid + 256) >> 5, bn = (tid & 31) * 4;
    uint4 ra0, ra1, rb0, rb1;
    ra0 = *(const uint4*)(Ap + (size_t)ar0 * (K / 2) + ac);
    ra1 = *(const uint4*)(Ap + (size_t)ar1 * (K / 2) + ac);
    rb0 = *(const uint4*)(Bp + (size_t)bk0 * N + bn);
    rb1 = *(const uint4*)(Bp + (size_t)bk1 * N + bn);

    for (int k0 = 0; k0 < K; k0 += 32) {
        *(uint4*)&As[ar0][ac] = ra0;
        *(uint4*)&As[ar1][ac] = ra1;
        *(uint4*)&Bs[bk0][bn] = rb0;
        *(uint4*)&Bs[bk1][bn] = rb1;
        __syncthreads();
        if (k0 + 32 < K) {
            int kh = (k0 + 32) / 2;
            ra0 = *(const uint4*)(Ap + (size_t)ar0 * (K / 2) + kh + ac);
            ra1 = *(const uint4*)(Ap + (size_t)ar1 * (K / 2) + kh + ac);
            rb0 = *(const uint4*)(Bp + (size_t)(kh + bk0) * N + bn);
            rb1 = *(const uint4*)(Bp + (size_t)(kh + bk1) * N + bn);
        }
#pragma unroll
        for (int ks = 0; ks < 2; ks++) {
            int kb2 = ks * 8;
            uint32_t af[2][4], bf[8][2];
#pragma unroll
            for (int mi = 0; mi < 2; mi++) {
                int r0 = wr + mi * 16;
                af[mi][0] = As[r0 + g][kb2 + tg];
                af[mi][1] = As[r0 + g + 8][kb2 + tg];
                af[mi][2] = As[r0 + g][kb2 + tg + 4];
                af[mi][3] = As[r0 + g + 8][kb2 + tg + 4];
            }
#pragma unroll
            for (int ni = 0; ni < 8; ni++) {
                bf[ni][0] = Bs[kb2 + tg][wc + ni * 8 + g];
                bf[ni][1] = Bs[kb2 + tg + 4][wc + ni * 8 + g];
            }
#pragma unroll
            for (int mi = 0; mi < 2; mi++)
#pragma unroll
                for (int ni = 0; ni < 8; ni++) mma_bf16(acc[mi][ni], af[mi], bf[ni]);
        }
        __syncthreads();
    }
    size_t rbase = (size_t)blockIdx.y * 128;
    if (blockIdx.x < 6) {
        uint32_t* C = (uint32_t*)g_xh;
        int cb = blockIdx.x * 128;
#pragma unroll
        for (int mi = 0; mi < 2; mi++)
#pragma unroll
            for (int ni = 0; ni < 8; ni++) {
                int r = wr + mi * 16 + g, c = cb + wc + ni * 8 + tg * 2;
                C[((rbase + r) * DI + c) >> 1]     = pack_bf2(acc[mi][ni][0], acc[mi][ni][1]);
                C[((rbase + r + 8) * DI + c) >> 1] = pack_bf2(acc[mi][ni][2], acc[mi][ni][3]);
            }
    } else {
        int cb = (blockIdx.x - 6) * 128;
#pragma unroll
        for (int mi = 0; mi < 2; mi++)
#pragma unroll
            for (int ni = 0; ni < 8; ni++) {
                int r = wr + mi * 16 + g, c = cb + wc + ni * 8 + tg * 2;
                *(float2*)(g_z + (rbase + r) * DI + c)     = make_float2(acc[mi][ni][0], acc[mi][ni][1]);
                *(float2*)(g_z + (rbase + r + 8) * DI + c) = make_float2(acc[mi][ni][2], acc[mi][ni][3]);
            }
    }
}

// ---------------- mm_out: out = x + (yf+yr) @ Wout (M=16384,N=384,K=768), fused add ----------------
__global__ __launch_bounds__(256, 2) void mm_out_bf16(const float* __restrict__ xres,
                                                      float* __restrict__ out) {
    const int K = 768, N = 384;
    __shared__ uint32_t As[128][20];
    __shared__ uint32_t Bs[16][136];
    int tid = threadIdx.x, lane = tid & 31, wid = tid >> 5;
    int wr = (wid & 3) * 32, wc = (wid >> 2) * 64;
    int g = lane >> 2, tg = lane & 3;
    const uint32_t* A0 = (const uint32_t*)g_y[0] + (size_t)blockIdx.y * 128 * (K / 2);
    const uint32_t* A1 = (const uint32_t*)g_y[1] + (size_t)blockIdx.y * 128 * (K / 2);
    const uint32_t* Bp = g_wout_p + blockIdx.x * 128;
    float acc[2][8][4] = {};

    int ar0 = tid >> 2, ar1 = (tid + 256) >> 2, ac = (tid & 3) * 4;
    int bk0 = tid >> 5, bk1 = (tid + 256) >> 5, bn = (tid & 31) * 4;
    uint4 ra0, ra1, sa0, sa1, rb0, rb1;
    ra0 = *(const uint4*)(A0 + (size_t)ar0 * (K / 2) + ac);
    sa0 = *(const uint4*)(A1 + (size_t)ar0 * (K / 2) + ac);
    ra1 = *(const uint4*)(A0 + (size_t)ar1 * (K / 2) + ac);
    sa1 = *(const uint4*)(A1 + (size_t)ar1 * (K / 2) + ac);
    rb0 = *(const uint4*)(Bp + (size_t)bk0 * N + bn);
    rb1 = *(const uint4*)(Bp + (size_t)bk1 * N + bn);

    for (int k0 = 0; k0 < K; k0 += 32) {
        As[ar0][ac + 0] = hadd2_bf2(ra0.x, sa0.x);
        As[ar0][ac + 1] = hadd2_bf2(ra0.y, sa0.y);
        As[ar0][ac + 2] = hadd2_bf2(ra0.z, sa0.z);
        As[ar0][ac + 3] = hadd2_bf2(ra0.w, sa0.w);
        As[ar1][ac + 0] = hadd2_bf2(ra1.x, sa1.x);
        As[ar1][ac + 1] = hadd2_bf2(ra1.y, sa1.y);
        As[ar1][ac + 2] = hadd2_bf2(ra1.z, sa1.z);
        As[ar1][ac + 3] = hadd2_bf2(ra1.w, sa1.w);
        *(uint4*)&Bs[bk0][bn] = rb0;
        *(uint4*)&Bs[bk1][bn] = rb1;
        __syncthreads();
        if (k0 + 32 < K) {
            int kh = (k0 + 32) / 2;
            ra0 = *(const uint4*)(A0 + (size_t)ar0 * (K / 2) + kh + ac);
            sa0 = *(const uint4*)(A1 + (size_t)ar0 * (K / 2) + kh + ac);
            ra1 = *(const uint4*)(A0 + (size_t)ar1 * (K / 2) + kh + ac);
            sa1 = *(const uint4*)(A1 + (size_t)ar1 * (K / 2) + kh + ac);
            rb0 = *(const uint4*)(Bp + (size_t)(kh + bk0) * N + bn);
            rb1 = *(const uint4*)(Bp + (size_t)(kh + bk1) * N + bn);
        }
#pragma unroll
        for (int ks = 0; ks < 2; ks++) {
            int kb2 = ks * 8;
            uint32_t af[2][4], bf[8][2];
#pragma unroll
            for (int mi = 0; mi < 2; mi++) {
                int r0 = wr + mi * 16;
                af[mi][0] = As[r0 + g][kb2 + tg];
                af[mi][1] = As[r0 + g + 8][kb2 + tg];
                af[mi][2] = As[r0 + g][kb2 + tg + 4];
                af[mi][3] = As[r0 + g + 8][kb2 + tg + 4];
            }
#pragma unroll
            for (int ni = 0; ni < 8; ni++) {
                bf[ni][0] = Bs[kb2 + tg][wc + ni * 8 + g];
                bf[ni][1] = Bs[kb2 + tg + 4][wc + ni * 8 + g];
            }
#pragma unroll
            for (int mi = 0; mi < 2; mi++)
#pragma unroll
                for (int ni = 0; ni < 8; ni++) mma_bf16(acc[mi][ni], af[mi], bf[ni]);
        }
        __syncthreads();
    }
    size_t rbase = (size_t)blockIdx.y * 128;
    int cbase = blockIdx.x * 128;
#pragma unroll
    for (int mi = 0; mi < 2; mi++)
#pragma unroll
        for (int ni = 0; ni < 8; ni++) {
            int r = wr + mi * 16 + g, c = wc + ni * 8 + tg * 2;
            size_t o0 = (rbase + r) * N + cbase + c;
            size_t o1 = (rbase + r + 8) * N + cbase + c;
            out[o0]     = acc[mi][ni][0] + xres[o0];
            out[o0 + 1] = acc[mi][ni][1] + xres[o0 + 1];
            out[o1]     = acc[mi][ni][2] + xres[o1];
            out[o1 + 1] = acc[mi][ni][3] + xres[o1 + 1];
        }
}

// ---------------- mm_x: dbc = xc @ Wx (M=16384,N=64->56,K=768), pipelined ----------------
__global__ __launch_bounds__(256, 2) void mm_x_bf16() {
    const int K = 768;
    int dir = blockIdx.z;
    __shared__ uint32_t As[128][20];
    __shared__ uint32_t Bs[16][72];
    int tid = threadIdx.x, lane = tid & 31, wid = tid >> 5;
    int wr = wid * 16;
    int g = lane >> 2, tg = lane & 3;
    const uint32_t* Ap = (const uint32_t*)g_xc[dir] + (size_t)blockIdx.y * 128 * (K / 2);
    const uint32_t* Bp = g_wx_p[dir];
    float acc[8][4] = {};

    int ar0 = tid >> 2, ar1 = (tid + 256) >> 2, ac = (tid & 3) * 4;
    int bk = tid >> 4, bn = (tid & 15) * 4;
    uint4 ra0, ra1, rb;
    ra0 = *(const uint4*)(Ap + (size_t)ar0 * (K / 2) + ac);
    ra1 = *(const uint4*)(Ap + (size_t)ar1 * (K / 2) + ac);
    rb  = *(const uint4*)(Bp + (size_t)bk * 64 + bn);

    for (int k0 = 0; k0 < K; k0 += 32) {
        *(uint4*)&As[ar0][ac] = ra0;
        *(uint4*)&As[ar1][ac] = ra1;
        *(uint4*)&Bs[bk][bn] = rb;
        __syncthreads();
        if (k0 + 32 < K) {
            int kh = (k0 + 32) / 2;
            ra0 = *(const uint4*)(Ap + (size_t)ar0 * (K / 2) + kh + ac);
            ra1 = *(const uint4*)(Ap + (size_t)ar1 * (K / 2) + kh + ac);
            rb  = *(const uint4*)(Bp + (size_t)(kh + bk) * 64 + bn);
        }
#pragma unroll
        for (int ks = 0; ks < 2; ks++) {
            int kb2 = ks * 8;
            uint32_t af[4], bf[8][2];
            af[0] = As[wr + g][kb2 + tg];
            af[1] = As[wr + g + 8][kb2 + tg];
            af[2] = As[wr + g][kb2 + tg + 4];
            af[3] = As[wr + g + 8][kb2 + tg + 4];
#pragma unroll
            for (int ni = 0; ni < 8; ni++) {
                bf[ni][0] = Bs[kb2 + tg][ni * 8 + g];
                bf[ni][1] = Bs[kb2 + tg + 4][ni * 8 + g];
            }
#pragma unroll
            for (int ni = 0; ni < 8; ni++) mma_bf16(acc[ni], af, bf[ni]);
        }
        __syncthreads();
    }
    size_t rbase = (size_t)blockIdx.y * 128;
#pragma unroll
    for (int ni = 0; ni < 8; ni++) {
        int c = ni * 8 + tg * 2;
        if (c < 56) {
            int r = wr + g;
            float* o0 = g_dbc[dir] + (rbase + r) * DBCW + c;
            float* o1 = g_dbc[dir] + (rbase + r + 8) * DBCW + c;
            o0[0] = acc[ni][0]; o0[1] = acc[ni][1];
            o1[0] = acc[ni][2]; o1[1] = acc[ni][3];
        }
    }
}

// ---------------- causal conv, chunk-parallel (8 chunks) + SiLU ----------------
__global__ __launch_bounds__(256) void conv_chunk_kernel(const float* __restrict__ cw_f,
                                                         const float* __restrict__ cb_f,
                                                         const float* __restrict__ cw_b,
                                                         const float* __restrict__ cb_b) {
    int dir = blockIdx.z;
    int bb = blockIdx.y >> 3, ch = blockIdx.y & 7;
    int d = blockIdx.x * 256 + threadIdx.x;
    int l0 = ch * CHT;
    const float* cw = dir ? cw_b : cw_f;
    float w0 = cw[d * 4 + 0], w1 = cw[d * 4 + 1], w2 = cw[d * 4 + 2], w3 = cw[d * 4 + 3];
    float bias = (dir ? cb_b : cb_f)[d];
    const __nv_bfloat16* xh = g_xh + (size_t)bb * Ll * DI + d;
    __nv_bfloat16* yo = g_xc[dir] + (size_t)bb * Ll * DI + d;
    // history: flipped-seq positions l0-3, l0-2, l0-1
    float x1 = 0.f, x2 = 0.f, x3 = 0.f;
    {
        int lk;
        lk = l0 - 1; if (lk >= 0) x1 = __bfloat162float(xh[(size_t)(dir ? (Ll - 1 - lk) : lk) * DI]);
        lk = l0 - 2; if (lk >= 0) x2 = __bfloat162float(xh[(size_t)(dir ? (Ll - 1 - lk) : lk) * DI]);
        lk = l0 - 3; if (lk >= 0) x3 = __bfloat162float(xh[(size_t)(dir ? (Ll - 1 - lk) : lk) * DI]);
    }
    for (int l = l0; l < l0 + CHT; l += 4) {
        float xv[4];
#pragma unroll
        for (int j = 0; j < 4; j++) {
            int lp = dir ? (Ll - 1 - (l + j)) : (l + j);
            xv[j] = __bfloat162float(xh[(size_t)lp * DI]);
        }
#pragma unroll
        for (int j = 0; j < 4; j++) {
            float a = bias + w3 * xv[j] + w2 * x1 + w1 * x2 + w0 * x3;
            x3 = x2; x2 = x1; x1 = xv[j];
            float s = a * (1.f / (1.f + __expf(-a)));
            yo[(size_t)(l + j) * DI] = __float2bfloat16(s);
        }
    }
}

// ---------------- dt_proj + softplus (float4 smem) ----------------
__global__ __launch_bounds__(256) void dtproj_kernel(const float* __restrict__ dtw_f,
                                                     const float* __restrict__ dtb_f,
                                                     const float* __restrict__ dtw_b,
                                                     const float* __restrict__ dtb_b) {
    int dir = blockIdx.z;
    int col = blockIdx.x * 256 + threadIdx.x;
    int r0 = blockIdx.y * 32;
    const float* Wd = dir ? dtw_b : dtw_f;
    float4 w[6];
#pragma unroll
    for (int j = 0; j < 6; j++) w[j] = *(const float4*)(Wd + col * DTR + j * 4);
    float bias = (dir ? dtb_b : dtb_f)[col];
    __shared__ __align__(16) float sdt[32 * DTR];
    if (threadIdx.x < 192) {
        int rr = threadIdx.x / 6, j = threadIdx.x % 6;
        *(float4*)&sdt[rr * DTR + j * 4] =
            *(const float4*)(g_dbc[dir] + (size_t)(r0 + rr) * DBCW + j * 4);
    }
    __syncthreads();
    for (int rr = 0; rr < 32; rr++) {
        float acc = bias;
#pragma unroll
        for (int j = 0; j < 6; j++) {
            float4 v = *(const float4*)&sdt[rr * DTR + j * 4];
            acc += v.x * w[j].x + v.y * w[j].y + v.z * w[j].z + v.w * w[j].w;
        }
        float sp = (acc > 20.f) ? acc : log1pf(__expf(acc));
        g_delta[dir][(size_t)(r0 + rr) * DI + col] = __float2bfloat16(sp);
    }
}

// ---------------- scan pass 1: per-chunk local states (h0=0) + sum(dt) ----------------
__global__ __launch_bounds__(64) void scan_pass1(const float* __restrict__ Alog_f,
                                                 const float* __restrict__ Alog_b) {
    int dir = blockIdx.z;
    int bb = blockIdx.y >> 3, ch = blockIdx.y & 7;
    int d = blockIdx.x * 64 + threadIdx.x;
    int tb = ch * CHT;
    const float* Alog = dir ? Alog_b : Alog_f;
    const __nv_bfloat16* delta = g_delta[dir] + ((size_t)bb * Ll + tb) * DI + d;
    const __nv_bfloat16* u     = g_xc[dir]   + ((size_t)bb * Ll + tb) * DI + d;
    const float* dbc           = g_dbc[dir]  + ((size_t)bb * Ll + tb) * DBCW;

    float A[NS];
#pragma unroll
    for (int n = 0; n < NS; n++) A[n] = -__expf(Alog[d * NS + n]);
    bool fast = true;
#pragma unroll
    for (int n = 1; n < NS; n++)
        fast = fast && (fabsf(A[n] - (float)(n + 1) * A[0]) <= 1e-5f * fabsf(A[n]));

    __shared__ float4 sB4[8][4];
    float h[NS];
#pragma unroll
    for (int n = 0; n < NS; n++) h[n] = 0.f;
    float sdt = 0.f;

    for (int t0 = 0; t0 < CHT; t0 += 8) {
        float dl[8], ul[8], ql[8];
#pragma unroll
        for (int i = 0; i < 8; i++) {
            dl[i] = __bfloat162float(delta[(size_t)(t0 + i) * DI]);
            ul[i] = __bfloat162float(u[(size_t)(t0 + i) * DI]);
            ql[i] = __expf(dl[i] * A[0]);
        }
        __syncthreads();
        if (threadIdx.x < 32) {
            int tt = threadIdx.x >> 2, j = threadIdx.x & 3;
            sB4[tt][j] = *(const float4*)(dbc + (size_t)(t0 + tt) * DBCW + DTR + j * 4);
        }
        __syncthreads();
#pragma unroll
        for (int i = 0; i < 8; i++) {
            float4 b0 = sB4[i][0], b1 = sB4[i][1], b2 = sB4[i][2], b3 = sB4[i][3];
            float Bv[NS] = {b0.x, b0.y, b0.z, b0.w, b1.x, b1.y, b1.z, b1.w,
                            b2.x, b2.y, b2.z, b2.w, b3.x, b3.y, b3.z, b3.w};
            float dt = dl[i];
            float du = dt * ul[i];
            sdt += dt;
            if (fast) {
                float q = ql[i];
                float q2 = q * q, q4 = q2 * q2, q8 = q4 * q4;
                float q3 = q2 * q, q5 = q4 * q, q6 = q4 * q2, q7 = q4 * q3;
                float pw[NS] = {q, q2, q3, q4, q5, q6, q7, q8,
                                q8 * q, q8 * q2, q8 * q3, q8 * q4,
                                q8 * q5, q8 * q6, q8 * q7, q8 * q8};
#pragma unroll
                for (int n = 0; n < NS; n++) h[n] = h[n] * pw[n] + du * Bv[n];
            } else {
#pragma unroll
                for (int n = 0; n < NS; n++) {
                    float dA = __expf(dt * A[n]);
                    h[n] = h[n] * dA + du * Bv[n];
                }
            }
        }
    }
#pragma unroll
    for (int n = 0; n < NS; n++) g_hc[dir][bb][ch][n][d] = h[n];
    g_dts[dir][bb][ch][d] = sdt;
}

// ---------------- scan pass 2: combine chunk states -> entry states ----------------
__global__ __launch_bounds__(256) void scan_pass2(const float* __restrict__ Alog_f,
                                                  const float* __restrict__ Alog_b) {
    int gid = blockIdx.x * 256 + threadIdx.x;
    int dir = gid / (Bb * DI);
    int rem = gid % (Bb * DI);
    int bb = rem / DI, d = rem % DI;
    const float* Alog = dir ? Alog_b : Alog_f;
    float A[NS];
#pragma unroll
    for (int n = 0; n < NS; n++) A[n] = -__expf(Alog[d * NS + n]);
    float entry[NS];
#pragma unroll
    for (int n = 0; n < NS; n++) entry[n] = 0.f;
#pragma unroll
    for (int ch = 0; ch < NCH; ch++) {
        float S = g_dts[dir][bb][ch][d];
        float hl[NS];
#pragma unroll
        for (int n = 0; n < NS; n++) {
            hl[n] = g_hc[dir][bb][ch][n][d];
            g_hc[dir][bb][ch][n][d] = entry[n];
        }
#pragma unroll
        for (int n = 0; n < NS; n++)
            entry[n] = hl[n] + __expf(A[n] * S) * entry[n];
    }
}

// ---------------- scan pass 3: full scan per chunk from entry state ----------------
__global__ __launch_bounds__(64) void scan_pass3(const float* __restrict__ Alog_f,
                                                 const float* __restrict__ Alog_b,
                                                 const float* __restrict__ Dv_f,
                                                 const float* __restrict__ Dv_b) {
    int dir = blockIdx.z;
    int bb = blockIdx.y >> 3, ch = blockIdx.y & 7;
    int d = blockIdx.x * 64 + threadIdx.x;
    int tb = ch * CHT;
    const float* Alog = dir ? Alog_b : Alog_f;
    const float* Dvp  = dir ? Dv_b  : Dv_f;
    const __nv_bfloat16* delta = g_delta[dir] + ((size_t)bb * Ll + tb) * DI + d;
    const __nv_bfloat16* u     = g_xc[dir]   + ((size_t)bb * Ll + tb) * DI + d;
    const float* dbc           = g_dbc[dir]  + ((size_t)bb * Ll + tb) * DBCW;
    const float* zb            = g_z + (size_t)bb * Ll * DI + d;
    __nv_bfloat16* yout        = g_y[dir] + (size_t)bb * Ll * DI + d;

    float A[NS];
#pragma unroll
    for (int n = 0; n < NS; n++) A[n] = -__expf(Alog[d * NS + n]);
    bool fast = true;
#pragma unroll
    for (int n = 1; n < NS; n++)
        fast = fast && (fabsf(A[n] - (float)(n + 1) * A[0]) <= 1e-5f * fabsf(A[n]));
    float Dv = Dvp[d];

    __shared__ float4 sBC[8][8];
    float h[NS];
#pragma unroll
    for (int n = 0; n < NS; n++) h[n] = g_hc[dir][bb][ch][n][d];

    for (int t0 = 0; t0 < CHT; t0 += 8) {
        float dl[8], ul[8], zl[8], ql[8];
#pragma unroll
        for (int i = 0; i < 8; i++) {
            dl[i] = __bfloat162float(delta[(size_t)(t0 + i) * DI]);
            ul[i] = __bfloat162float(u[(size_t)(t0 + i) * DI]);
            int t = tb + t0 + i;
            int op = dir ? (Ll - 1 - t) : t;
            zl[i] = zb[(size_t)op * DI];
            ql[i] = __expf(dl[i] * A[0]);
        }
        __syncthreads();
        {
            int tt = threadIdx.x >> 3, j = threadIdx.x & 7;
            sBC[tt][j] = *(const float4*)(dbc + (size_t)(t0 + tt) * DBCW + DTR + j * 4);
        }
        __syncthreads();
#pragma unroll
        for (int i = 0; i < 8; i++) {
            float4 b0 = sBC[i][0], b1 = sBC[i][1], b2 = sBC[i][2], b3 = sBC[i][3];
            float4 c0 = sBC[i][4], c1 = sBC[i][5], c2 = sBC[i][6], c3 = sBC[i][7];
            float Bv[NS] = {b0.x, b0.y, b0.z, b0.w, b1.x, b1.y, b1.z, b1.w,
                            b2.x, b2.y, b2.z, b2.w, b3.x, b3.y, b3.z, b3.w};
            float Cv[NS] = {c0.x, c0.y, c0.z, c0.w, c1.x, c1.y, c1.z, c1.w,
                            c2.x, c2.y, c2.z, c2.w, c3.x, c3.y, c3.z, c3.w};
            float dt = dl[i];
            float du = dt * ul[i];
            float y = 0.f;
            if (fast) {
                float q = ql[i];
                float q2 = q * q, q4 = q2 * q2, q8 = q4 * q4;
                float q3 = q2 * q, q5 = q4 * q, q6 = q4 * q2, q7 = q4 * q3;
                float pw[NS] = {q, q2, q3, q4, q5, q6, q7, q8,
                                q8 * q, q8 * q2, q8 * q3, q8 * q4,
                                q8 * q5, q8 * q6, q8 * q7, q8 * q8};
#pragma unroll
                for (int n = 0; n < NS; n++) {
                    h[n] = h[n] * pw[n] + du * Bv[n];
                    y += h[n] * Cv[n];
                }
            } else {
#pragma unroll
                for (int n = 0; n < NS; n++) {
                    float dA = __expf(dt * A[n]);
                    h[n] = h[n] * dA + du * Bv[n];
                    y += h[n] * Cv[n];
                }
            }
            y += ul[i] * Dv;
            float z = zl[i];
            float sz = z * (1.f / (1.f + __expf(-z)));
            int t = tb + t0 + i;
            int op = dir ? (Ll - 1 - t) : t;
            yout[(size_t)op * DI] = __float2bfloat16(y * sz);
        }
    }
}

// ---------------- launch ----------------
extern "C" void kernel_launch(void* const* d_in, const int* in_sizes, int n_in,
                              void* d_out, int out_size) {
    const float* x        = (const float*)d_in[0];
    const float* ln_w     = (const float*)d_in[1];
    const float* ln_b     = (const float*)d_in[2];
    const float* in_proj  = (const float*)d_in[3];
    const float* out_proj = (const float*)d_in[4];
    const float* cw_f     = (const float*)d_in[5];
    const float* cb_f     = (const float*)d_in[6];
    const float* xw_f     = (const float*)d_in[7];
    const float* dtw_f    = (const float*)d_in[8];
    const float* dtb_f    = (const float*)d_in[9];
    const float* Alog_f   = (const float*)d_in[10];
    const float* Dv_f     = (const float*)d_in[11];
    const float* cw_b     = (const float*)d_in[12];
    const float* cb_b     = (const float*)d_in[13];
    const float* xw_b     = (const float*)d_in[14];
    const float* dtw_b    = (const float*)d_in[15];
    const float* dtb_b    = (const float*)d_in[16];
    const float* Alog_b   = (const float*)d_in[17];
    const float* Dv_b     = (const float*)d_in[18];
    float* out = (float*)d_out;

    ln_kernel<<<BLr, 384>>>(x, ln_w, ln_b);
    transpose_all<<<(TIN + TOUT + TX + 255) / 256, 256>>>(in_proj, out_proj, xw_f, xw_b);
    mm_in_bf16<<<dim3(12, 128), 256>>>();
    conv_chunk_kernel<<<dim3(3, Bb * NCH, 2), 256>>>(cw_f, cb_f, cw_b, cb_b);
    mm_x_bf16<<<dim3(1, 128, 2), 256>>>();
    dtproj_kernel<<<dim3(3, BLr / 32, 2), 256>>>(dtw_f, dtb_f, dtw_b, dtb_b);
    scan_pass1<<<dim3(12, 128, 2), 64>>>(Alog_f, Alog_b);
    scan_pass2<<<(2 * Bb * DI) / 256, 256>>>(Alog_f, Alog_b);
    scan_pass3<<<dim3(12, 128, 2), 64>>>(Alog_f, Alog_b, Dv_f, Dv_b);
    mm_out_bf16<<<dim3(3, 128), 256>>>(x, out);
}

// round 10
// speedup vs baseline: 4.7401x; 1.0477x over previous
#include <cuda_runtime.h>
#include <cuda_bf16.h>
#include <cstdint>

#define Bb   16
#define Ll   1024
#define DM   384
#define DI   768
#define NS   16
#define DTR  24
#define DBCW 56            // DTR + 2*NS
#define BLr  16384         // Bb*Ll
#define NCH  8             // scan chunks
#define CHT  128           // steps per chunk

// ---------------- scratch (device globals; no allocations) ----------------
__device__ __nv_bfloat16 g_xnb[(size_t)BLr * DM];
__device__ uint32_t g_win_p[(size_t)(DM / 2) * 1536];
__device__ uint32_t g_wout_p[(size_t)(DI / 2) * DM];
__device__ uint32_t g_wx_p[2][(size_t)(DI / 2) * 64];
__device__ __nv_bfloat16 g_xh[(size_t)BLr * DI];
__device__ float         g_z[(size_t)BLr * DI];
__device__ __nv_bfloat16 g_xc[2][(size_t)BLr * DI];
__device__ float         g_dbc[2][(size_t)BLr * DBCW];
__device__ __nv_bfloat16 g_delta[2][(size_t)BLr * DI];
__device__ __nv_bfloat16 g_y[2][(size_t)BLr * DI];
__device__ float g_hc[2][Bb][NCH][NS][DI];
__device__ float g_dts[2][Bb][NCH][DI];

// ---------------- bf16 helpers ----------------
__device__ __forceinline__ uint32_t pack_bf2(float lo, float hi) {
    uint32_t r; asm("cvt.rn.bf16x2.f32 %0, %1, %2;" : "=r"(r) : "f"(hi), "f"(lo)); return r;
}
__device__ __forceinline__ float2 unpk_bf2(uint32_t v) {
    __nv_bfloat162 b = *(__nv_bfloat162*)&v; return __bfloat1622float2(b);
}
__device__ __forceinline__ uint32_t hadd2_bf2(uint32_t a, uint32_t b) {
    __nv_bfloat162 r = __hadd2(*(__nv_bfloat162*)&a, *(__nv_bfloat162*)&b);
    return *(uint32_t*)&r;
}
__device__ __forceinline__ void mma_bf16(float (&d)[4], const uint32_t (&a)[4], const uint32_t (&b)[2]) {
    asm volatile("mma.sync.aligned.m16n8k16.row.col.f32.bf16.bf16.f32 "
                 "{%0,%1,%2,%3}, {%4,%5,%6,%7}, {%8,%9}, {%0,%1,%2,%3};"
                 : "+f"(d[0]), "+f"(d[1]), "+f"(d[2]), "+f"(d[3])
                 : "r"(a[0]), "r"(a[1]), "r"(a[2]), "r"(a[3]), "r"(b[0]), "r"(b[1]));
}

// ---------------- LayerNorm: warp per row ----------------
__global__ __launch_bounds__(256) void ln_kernel(const float* __restrict__ x,
                                                 const float* __restrict__ w,
                                                 const float* __restrict__ b) {
    int warp = threadIdx.x >> 5, lane = threadIdx.x & 31;
    int r = blockIdx.x * 8 + warp;
    const float2* xr = (const float2*)(x + (size_t)r * DM);
    float2 v[6];
    float s = 0.f, s2 = 0.f;
#pragma unroll
    for (int i = 0; i < 6; i++) {
        v[i] = xr[i * 32 + lane];
        s += v[i].x + v[i].y;
        s2 += v[i].x * v[i].x + v[i].y * v[i].y;
    }
#pragma unroll
    for (int o = 16; o; o >>= 1) {
        s  += __shfl_xor_sync(0xffffffffu, s, o);
        s2 += __shfl_xor_sync(0xffffffffu, s2, o);
    }
    float mu = s / DM;
    float rstd = rsqrtf(s2 / DM - mu * mu + 1e-5f);
    uint32_t* o = (uint32_t*)g_xnb + (size_t)r * (DM / 2);
#pragma unroll
    for (int i = 0; i < 6; i++) {
        int idx = i * 32 + lane;
        float2 wv = *(const float2*)(w + 2 * idx);
        float2 bv = *(const float2*)(b + 2 * idx);
        o[idx] = pack_bf2((v[i].x - mu) * rstd * wv.x + bv.x,
                          (v[i].y - mu) * rstd * wv.y + bv.y);
    }
}

// ---------------- fused weight transposes + bf16 packing ----------------
#define TIN  (192 * 1536)
#define TOUT (384 * 384)
#define TX   (384 * 64)
__global__ void transpose_all(const float* __restrict__ Win, const float* __restrict__ Wout,
                              const float* __restrict__ Wxf, const float* __restrict__ Wxb) {
    int i = blockIdx.x * 256 + threadIdx.x;
    if (i < TIN) {
        int k2 = i / 1536, n = i % 1536;
        float2 v = *(const float2*)(Win + (size_t)n * 384 + 2 * k2);
        g_win_p[i] = pack_bf2(v.x, v.y);
    } else if (i < TIN + TOUT) {
        int j = i - TIN;
        int k2 = j / 384, n = j % 384;
        float2 v = *(const float2*)(Wout + (size_t)n * 768 + 2 * k2);
        g_wout_p[j] = pack_bf2(v.x, v.y);
    } else if (i < TIN + TOUT + TX) {
        int j = i - TIN - TOUT;
        int k2 = j / 64, n = j % 64;
        if (n < 56) {
            float2 vf = *(const float2*)(Wxf + (size_t)n * 768 + 2 * k2);
            float2 vb = *(const float2*)(Wxb + (size_t)n * 768 + 2 * k2);
            g_wx_p[0][j] = pack_bf2(vf.x, vf.y);
            g_wx_p[1][j] = pack_bf2(vb.x, vb.y);
        } else {
            g_wx_p[0][j] = 0u; g_wx_p[1][j] = 0u;
        }
    }
}

// ---------------- mm_in: [xh|z] = xn @ Win  (M=16384,N=1536,K=384), dbuf 1-sync ----------------
__global__ __launch_bounds__(256, 2) void mm_in_bf16() {
    const int K = 384, N = 1536, T = 12;
    __shared__ uint32_t As[2][128][20];
    __shared__ uint32_t Bs[2][16][136];
    int tid = threadIdx.x, lane = tid & 31, wid = tid >> 5;
    int wr = (wid & 3) * 32, wc = (wid >> 2) * 64;
    int g = lane >> 2, tg = lane & 3;
    const uint32_t* Ap = (const uint32_t*)g_xnb + (size_t)blockIdx.y * 128 * (K / 2);
    const uint32_t* Bp = g_win_p + blockIdx.x * 128;
    float acc[2][8][4] = {};

    int ar0 = tid >> 2, ar1 = (tid + 256) >> 2, ac = (tid & 3) * 4;
    int bk0 = tid >> 5, bk1 = (tid + 256) >> 5, bn = (tid & 31) * 4;
    uint4 ra0, ra1, rb0, rb1;
    ra0 = *(const uint4*)(Ap + (size_t)ar0 * (K / 2) + ac);
    ra1 = *(const uint4*)(Ap + (size_t)ar1 * (K / 2) + ac);
    rb0 = *(const uint4*)(Bp + (size_t)bk0 * N + bn);
    rb1 = *(const uint4*)(Bp + (size_t)bk1 * N + bn);

    for (int i = 0; i < T; i++) {
        int s = i & 1;
        *(uint4*)&As[s][ar0][ac] = ra0;
        *(uint4*)&As[s][ar1][ac] = ra1;
        *(uint4*)&Bs[s][bk0][bn] = rb0;
        *(uint4*)&Bs[s][bk1][bn] = rb1;
        __syncthreads();
        if (i + 1 < T) {
            int kh = (i + 1) * 16;
            ra0 = *(const uint4*)(Ap + (size_t)ar0 * (K / 2) + kh + ac);
            ra1 = *(const uint4*)(Ap + (size_t)ar1 * (K / 2) + kh + ac);
            rb0 = *(const uint4*)(Bp + (size_t)(kh + bk0) * N + bn);
            rb1 = *(const uint4*)(Bp + (size_t)(kh + bk1) * N + bn);
        }
#pragma unroll
        for (int ks = 0; ks < 2; ks++) {
            int kb2 = ks * 8;
            uint32_t af[2][4], bf[8][2];
#pragma unroll
            for (int mi = 0; mi < 2; mi++) {
                int r0 = wr + mi * 16;
                af[mi][0] = As[s][r0 + g][kb2 + tg];
                af[mi][1] = As[s][r0 + g + 8][kb2 + tg];
                af[mi][2] = As[s][r0 + g][kb2 + tg + 4];
                af[mi][3] = As[s][r0 + g + 8][kb2 + tg + 4];
            }
#pragma unroll
            for (int ni = 0; ni < 8; ni++) {
                bf[ni][0] = Bs[s][kb2 + tg][wc + ni * 8 + g];
                bf[ni][1] = Bs[s][kb2 + tg + 4][wc + ni * 8 + g];
            }
#pragma unroll
            for (int mi = 0; mi < 2; mi++)
#pragma unroll
                for (int ni = 0; ni < 8; ni++) mma_bf16(acc[mi][ni], af[mi], bf[ni]);
        }
        __syncthreads();
    }
    size_t rbase = (size_t)blockIdx.y * 128;
    if (blockIdx.x < 6) {
        uint32_t* C = (uint32_t*)g_xh;
        int cb = blockIdx.x * 128;
#pragma unroll
        for (int mi = 0; mi < 2; mi++)
#pragma unroll
            for (int ni = 0; ni < 8; ni++) {
                int r = wr + mi * 16 + g, c = cb + wc + ni * 8 + tg * 2;
                C[((rbase + r) * DI + c) >> 1]     = pack_bf2(acc[mi][ni][0], acc[mi][ni][1]);
                C[((rbase + r + 8) * DI + c) >> 1] = pack_bf2(acc[mi][ni][2], acc[mi][ni][3]);
            }
    } else {
        int cb = (blockIdx.x - 6) * 128;
#pragma unroll
        for (int mi = 0; mi < 2; mi++)
#pragma unroll
            for (int ni = 0; ni < 8; ni++) {
                int r = wr + mi * 16 + g, c = cb + wc + ni * 8 + tg * 2;
                *(float2*)(g_z + (rbase + r) * DI + c)     = make_float2(acc[mi][ni][0], acc[mi][ni][1]);
                *(float2*)(g_z + (rbase + r + 8) * DI + c) = make_float2(acc[mi][ni][2], acc[mi][ni][3]);
            }
    }
}

// ---------------- mm_out: out = x + (yf+yr) @ Wout (M=16384,N=384,K=768), dbuf 1-sync ----------------
__global__ __launch_bounds__(256, 2) void mm_out_bf16(const float* __restrict__ xres,
                                                      float* __restrict__ out) {
    const int K = 768, N = 384, T = 24;
    __shared__ uint32_t As[2][128][20];
    __shared__ uint32_t Bs[2][16][136];
    int tid = threadIdx.x, lane = tid & 31, wid = tid >> 5;
    int wr = (wid & 3) * 32, wc = (wid >> 2) * 64;
    int g = lane >> 2, tg = lane & 3;
    const uint32_t* A0 = (const uint32_t*)g_y[0] + (size_t)blockIdx.y * 128 * (K / 2);
    const uint32_t* A1 = (const uint32_t*)g_y[1] + (size_t)blockIdx.y * 128 * (K / 2);
    const uint32_t* Bp = g_wout_p + blockIdx.x * 128;
    float acc[2][8][4] = {};

    int ar0 = tid >> 2, ar1 = (tid + 256) >> 2, ac = (tid & 3) * 4;
    int bk0 = tid >> 5, bk1 = (tid + 256) >> 5, bn = (tid & 31) * 4;
    uint4 ra0, ra1, sa0, sa1, rb0, rb1;
    ra0 = *(const uint4*)(A0 + (size_t)ar0 * (K / 2) + ac);
    sa0 = *(const uint4*)(A1 + (size_t)ar0 * (K / 2) + ac);
    ra1 = *(const uint4*)(A0 + (size_t)ar1 * (K / 2) + ac);
    sa1 = *(const uint4*)(A1 + (size_t)ar1 * (K / 2) + ac);
    rb0 = *(const uint4*)(Bp + (size_t)bk0 * N + bn);
    rb1 = *(const uint4*)(Bp + (size_t)bk1 * N + bn);

    for (int i = 0; i < T; i++) {
        int s = i & 1;
        As[s][ar0][ac + 0] = hadd2_bf2(ra0.x, sa0.x);
        As[s][ar0][ac + 1] = hadd2_bf2(ra0.y, sa0.y);
        As[s][ar0][ac + 2] = hadd2_bf2(ra0.z, sa0.z);
        As[s][ar0][ac + 3] = hadd2_bf2(ra0.w, sa0.w);
        As[s][ar1][ac + 0] = hadd2_bf2(ra1.x, sa1.x);
        As[s][ar1][ac + 1] = hadd2_bf2(ra1.y, sa1.y);
        As[s][ar1][ac + 2] = hadd2_bf2(ra1.z, sa1.z);
        As[s][ar1][ac + 3] = hadd2_bf2(ra1.w, sa1.w);
        *(uint4*)&Bs[s][bk0][bn] = rb0;
        *(uint4*)&Bs[s][bk1][bn] = rb1;
        __syncthreads();
        if (i + 1 < T) {
            int kh = (i + 1) * 16;
            ra0 = *(const uint4*)(A0 + (size_t)ar0 * (K / 2) + kh + ac);
            sa0 = *(const uint4*)(A1 + (size_t)ar0 * (K / 2) + kh + ac);
            ra1 = *(const uint4*)(A0 + (size_t)ar1 * (K / 2) + kh + ac);
            sa1 = *(const uint4*)(A1 + (size_t)ar1 * (K / 2) + kh + ac);
            rb0 = *(const uint4*)(Bp + (size_t)(kh + bk0) * N + bn);
            rb1 = *(const uint4*)(Bp + (size_t)(kh + bk1) * N + bn);
        }
#pragma unroll
        for (int ks = 0; ks < 2; ks++) {
            int kb2 = ks * 8;
            uint32_t af[2][4], bf[8][2];
#pragma unroll
            for (int mi = 0; mi < 2; mi++) {
                int r0 = wr + mi * 16;
                af[mi][0] = As[s][r0 + g][kb2 + tg];
                af[mi][1] = As[s][r0 + g + 8][kb2 + tg];
                af[mi][2] = As[s][r0 + g][kb2 + tg + 4];
                af[mi][3] = As[s][r0 + g + 8][kb2 + tg + 4];
            }
#pragma unroll
            for (int ni = 0; ni < 8; ni++) {
                bf[ni][0] = Bs[s][kb2 + tg][wc + ni * 8 + g];
                bf[ni][1] = Bs[s][kb2 + tg + 4][wc + ni * 8 + g];
            }
#pragma unroll
            for (int mi = 0; mi < 2; mi++)
#pragma unroll
                for (int ni = 0; ni < 8; ni++) mma_bf16(acc[mi][ni], af[mi], bf[ni]);
        }
        __syncthreads();
    }
    size_t rbase = (size_t)blockIdx.y * 128;
    int cbase = blockIdx.x * 128;
#pragma unroll
    for (int mi = 0; mi < 2; mi++)
#pragma unroll
        for (int ni = 0; ni < 8; ni++) {
            int r = wr + mi * 16 + g, c = wc + ni * 8 + tg * 2;
            size_t o0 = (rbase + r) * N + cbase + c;
            size_t o1 = (rbase + r + 8) * N + cbase + c;
            out[o0]     = acc[mi][ni][0] + xres[o0];
            out[o0 + 1] = acc[mi][ni][1] + xres[o0 + 1];
            out[o1]     = acc[mi][ni][2] + xres[o1];
            out[o1 + 1] = acc[mi][ni][3] + xres[o1 + 1];
        }
}

// ---------------- mm_x: dbc = xc @ Wx (M=16384,N=64->56,K=768), dbuf 1-sync ----------------
__global__ __launch_bounds__(256, 2) void mm_x_bf16() {
    const int K = 768, T = 24;
    int dir = blockIdx.z;
    __shared__ uint32_t As[2][128][20];
    __shared__ uint32_t Bs[2][16][72];
    int tid = threadIdx.x, lane = tid & 31, wid = tid >> 5;
    int wr = wid * 16;
    int g = lane >> 2, tg = lane & 3;
    const uint32_t* Ap = (const uint32_t*)g_xc[dir] + (size_t)blockIdx.y * 128 * (K / 2);
    const uint32_t* Bp = g_wx_p[dir];
    float acc[8][4] = {};

    int ar0 = tid >> 2, ar1 = (tid + 256) >> 2, ac = (tid & 3) * 4;
    int bk = tid >> 4, bn = (tid & 15) * 4;
    uint4 ra0, ra1, rb;
    ra0 = *(const uint4*)(Ap + (size_t)ar0 * (K / 2) + ac);
    ra1 = *(const uint4*)(Ap + (size_t)ar1 * (K / 2) + ac);
    rb  = *(const uint4*)(Bp + (size_t)bk * 64 + bn);

    for (int i = 0; i < T; i++) {
        int s = i & 1;
        *(uint4*)&As[s][ar0][ac] = ra0;
        *(uint4*)&As[s][ar1][ac] = ra1;
        *(uint4*)&Bs[s][bk][bn] = rb;
        __syncthreads();
        if (i + 1 < T) {
            int kh = (i + 1) * 16;
            ra0 = *(const uint4*)(Ap + (size_t)ar0 * (K / 2) + kh + ac);
            ra1 = *(const uint4*)(Ap + (size_t)ar1 * (K / 2) + kh + ac);
            rb  = *(const uint4*)(Bp + (size_t)(kh + bk) * 64 + bn);
        }
#pragma unroll
        for (int ks = 0; ks < 2; ks++) {
            int kb2 = ks * 8;
            uint32_t af[4], bf[8][2];
            af[0] = As[s][wr + g][kb2 + tg];
            af[1] = As[s][wr + g + 8][kb2 + tg];
            af[2] = As[s][wr + g][kb2 + tg + 4];
            af[3] = As[s][wr + g + 8][kb2 + tg + 4];
#pragma unroll
            for (int ni = 0; ni < 8; ni++) {
                bf[ni][0] = Bs[s][kb2 + tg][ni * 8 + g];
                bf[ni][1] = Bs[s][kb2 + tg + 4][ni * 8 + g];
            }
#pragma unroll
            for (int ni = 0; ni < 8; ni++) mma_bf16(acc[ni], af, bf[ni]);
        }
        __syncthreads();
    }
    size_t rbase = (size_t)blockIdx.y * 128;
#pragma unroll
    for (int ni = 0; ni < 8; ni++) {
        int c = ni * 8 + tg * 2;
        if (c < 56) {
            int r = wr + g;
            float* o0 = g_dbc[dir] + (rbase + r) * DBCW + c;
            float* o1 = g_dbc[dir] + (rbase + r + 8) * DBCW + c;
            o0[0] = acc[ni][0]; o0[1] = acc[ni][1];
            o1[0] = acc[ni][2]; o1[1] = acc[ni][3];
        }
    }
}

// ---------------- causal conv, chunk-parallel, 2 channels/thread, packed ----------------
__global__ __launch_bounds__(384) void conv_chunk_kernel(const float* __restrict__ cw_f,
                                                         const float* __restrict__ cb_f,
                                                         const float* __restrict__ cw_b,
                                                         const float* __restrict__ cb_b) {
    int dir = blockIdx.z;
    int bb = blockIdx.y >> 3, ch = blockIdx.y & 7;
    int d2 = threadIdx.x;            // channel pair 0..383
    int d = d2 * 2;
    int l0 = ch * CHT;
    const float* cw = dir ? cw_b : cw_f;
    float4 wa = *(const float4*)(cw + d * 4);
    float4 wb = *(const float4*)(cw + d * 4 + 4);
    float2 bias = *(const float2*)((dir ? cb_b : cb_f) + d);
    const uint32_t* xp = (const uint32_t*)g_xh + (size_t)bb * Ll * (DI / 2) + d2;
    uint32_t* yo = (uint32_t*)g_xc[dir] + ((size_t)bb * Ll + l0) * (DI / 2) + d2;
    float a1 = 0.f, a2 = 0.f, a3 = 0.f;   // channel d history
    float b1 = 0.f, b2 = 0.f, b3 = 0.f;   // channel d+1 history
    {
        int lk;
        lk = l0 - 1; if (lk >= 0) { float2 v = unpk_bf2(xp[(size_t)(dir ? (Ll - 1 - lk) : lk) * (DI / 2)]); a1 = v.x; b1 = v.y; }
        lk = l0 - 2; if (lk >= 0) { float2 v = unpk_bf2(xp[(size_t)(dir ? (Ll - 1 - lk) : lk) * (DI / 2)]); a2 = v.x; b2 = v.y; }
        lk = l0 - 3; if (lk >= 0) { float2 v = unpk_bf2(xp[(size_t)(dir ? (Ll - 1 - lk) : lk) * (DI / 2)]); a3 = v.x; b3 = v.y; }
    }
    const uint32_t* xq = xp + (size_t)(dir ? (Ll - 1 - l0) : l0) * (DI / 2);
    intptr_t step = (dir ? -(intptr_t)(DI / 2) : (intptr_t)(DI / 2));
    for (int l = 0; l < CHT; l += 4) {
        float2 xv[4];
#pragma unroll
        for (int j = 0; j < 4; j++) { xv[j] = unpk_bf2(*xq); xq += step; }
#pragma unroll
        for (int j = 0; j < 4; j++) {
            float sa = bias.x + wa.w * xv[j].x + wa.z * a1 + wa.y * a2 + wa.x * a3;
            float sb = bias.y + wb.w * xv[j].y + wb.z * b1 + wb.y * b2 + wb.x * b3;
            a3 = a2; a2 = a1; a1 = xv[j].x;
            b3 = b2; b2 = b1; b1 = xv[j].y;
            sa = sa * (1.f / (1.f + __expf(-sa)));
            sb = sb * (1.f / (1.f + __expf(-sb)));
            yo[(size_t)(l + j) * (DI / 2)] = pack_bf2(sa, sb);
        }
    }
}

// ---------------- dt_proj + softplus (float4 smem) ----------------
__global__ __launch_bounds__(256) void dtproj_kernel(const float* __restrict__ dtw_f,
                                                     const float* __restrict__ dtb_f,
                                                     const float* __restrict__ dtw_b,
                                                     const float* __restrict__ dtb_b) {
    int dir = blockIdx.z;
    int col = blockIdx.x * 256 + threadIdx.x;
    int r0 = blockIdx.y * 32;
    const float* Wd = dir ? dtw_b : dtw_f;
    float4 w[6];
#pragma unroll
    for (int j = 0; j < 6; j++) w[j] = *(const float4*)(Wd + col * DTR + j * 4);
    float bias = (dir ? dtb_b : dtb_f)[col];
    __shared__ __align__(16) float sdt[32 * DTR];
    if (threadIdx.x < 192) {
        int rr = threadIdx.x / 6, j = threadIdx.x % 6;
        *(float4*)&sdt[rr * DTR + j * 4] =
            *(const float4*)(g_dbc[dir] + (size_t)(r0 + rr) * DBCW + j * 4);
    }
    __syncthreads();
    for (int rr = 0; rr < 32; rr++) {
        float acc = bias;
#pragma unroll
        for (int j = 0; j < 6; j++) {
            float4 v = *(const float4*)&sdt[rr * DTR + j * 4];
            acc += v.x * w[j].x + v.y * w[j].y + v.z * w[j].z + v.w * w[j].w;
        }
        float sp = (acc > 20.f) ? acc : log1pf(__expf(acc));
        g_delta[dir][(size_t)(r0 + rr) * DI + col] = __float2bfloat16(sp);
    }
}

// ---------------- scan pass 1: per-chunk local states (h0=0) + sum(dt) ----------------
__global__ __launch_bounds__(64) void scan_pass1(const float* __restrict__ Alog_f,
                                                 const float* __restrict__ Alog_b) {
    int dir = blockIdx.z;
    int bb = blockIdx.y >> 3, ch = blockIdx.y & 7;
    int d = blockIdx.x * 64 + threadIdx.x;
    int tb = ch * CHT;
    const float* Alog = dir ? Alog_b : Alog_f;
    const __nv_bfloat16* delta = g_delta[dir] + ((size_t)bb * Ll + tb) * DI + d;
    const __nv_bfloat16* u     = g_xc[dir]   + ((size_t)bb * Ll + tb) * DI + d;
    const float* dbc           = g_dbc[dir]  + ((size_t)bb * Ll + tb) * DBCW;

    float A[NS];
#pragma unroll
    for (int n = 0; n < NS; n++) A[n] = -__expf(Alog[d * NS + n]);
    bool fast = true;
#pragma unroll
    for (int n = 1; n < NS; n++)
        fast = fast && (fabsf(A[n] - (float)(n + 1) * A[0]) <= 1e-5f * fabsf(A[n]));

    __shared__ float4 sB4[8][4];
    float h[NS];
#pragma unroll
    for (int n = 0; n < NS; n++) h[n] = 0.f;
    float sdt = 0.f;

    for (int t0 = 0; t0 < CHT; t0 += 8) {
        float dl[8], ul[8], ql[8];
#pragma unroll
        for (int i = 0; i < 8; i++) {
            dl[i] = __bfloat162float(delta[(size_t)(t0 + i) * DI]);
            ul[i] = __bfloat162float(u[(size_t)(t0 + i) * DI]);
            ql[i] = __expf(dl[i] * A[0]);
        }
        __syncthreads();
        if (threadIdx.x < 32) {
            int tt = threadIdx.x >> 2, j = threadIdx.x & 3;
            sB4[tt][j] = *(const float4*)(dbc + (size_t)(t0 + tt) * DBCW + DTR + j * 4);
        }
        __syncthreads();
#pragma unroll
        for (int i = 0; i < 8; i++) {
            float4 b0 = sB4[i][0], b1 = sB4[i][1], b2 = sB4[i][2], b3 = sB4[i][3];
            float Bv[NS] = {b0.x, b0.y, b0.z, b0.w, b1.x, b1.y, b1.z, b1.w,
                            b2.x, b2.y, b2.z, b2.w, b3.x, b3.y, b3.z, b3.w};
            float dt = dl[i];
            float du = dt * ul[i];
            sdt += dt;
            if (fast) {
                float q = ql[i];
                float q2 = q * q, q4 = q2 * q2, q8 = q4 * q4;
                float q3 = q2 * q, q5 = q4 * q, q6 = q4 * q2, q7 = q4 * q3;
                float pw[NS] = {q, q2, q3, q4, q5, q6, q7, q8,
                                q8 * q, q8 * q2, q8 * q3, q8 * q4,
                                q8 * q5, q8 * q6, q8 * q7, q8 * q8};
#pragma unroll
                for (int n = 0; n < NS; n++) h[n] = h[n] * pw[n] + du * Bv[n];
            } else {
#pragma unroll
                for (int n = 0; n < NS; n++) {
                    float dA = __expf(dt * A[n]);
                    h[n] = h[n] * dA + du * Bv[n];
                }
            }
        }
    }
#pragma unroll
    for (int n = 0; n < NS; n++) g_hc[dir][bb][ch][n][d] = h[n];
    g_dts[dir][bb][ch][d] = sdt;
}

// ---------------- scan pass 3: combine entry inline, then full scan ----------------
__global__ __launch_bounds__(64) void scan_pass3(const float* __restrict__ Alog_f,
                                                 const float* __restrict__ Alog_b,
                                                 const float* __restrict__ Dv_f,
                                                 const float* __restrict__ Dv_b) {
    int dir = blockIdx.z;
    int bb = blockIdx.y >> 3, ch = blockIdx.y & 7;
    int d = blockIdx.x * 64 + threadIdx.x;
    int tb = ch * CHT;
    const float* Alog = dir ? Alog_b : Alog_f;
    const float* Dvp  = dir ? Dv_b  : Dv_f;
    const __nv_bfloat16* delta = g_delta[dir] + ((size_t)bb * Ll + tb) * DI + d;
    const __nv_bfloat16* u     = g_xc[dir]   + ((size_t)bb * Ll + tb) * DI + d;
    const float* dbc           = g_dbc[dir]  + ((size_t)bb * Ll + tb) * DBCW;
    const float* zb            = g_z + (size_t)bb * Ll * DI + d;
    __nv_bfloat16* yout        = g_y[dir] + (size_t)bb * Ll * DI + d;

    float A[NS];
#pragma unroll
    for (int n = 0; n < NS; n++) A[n] = -__expf(Alog[d * NS + n]);
    bool fast = true;
#pragma unroll
    for (int n = 1; n < NS; n++)
        fast = fast && (fabsf(A[n] - (float)(n + 1) * A[0]) <= 1e-5f * fabsf(A[n]));
    float Dv = Dvp[d];

    // entry state: sequentially combine chunks 0..ch-1 (same math as old pass2)
    float h[NS];
#pragma unroll
    for (int n = 0; n < NS; n++) h[n] = 0.f;
    for (int j = 0; j < ch; j++) {
        float S = g_dts[dir][bb][j][d];
        if (fast) {
            float r = __expf(A[0] * S);
            float r2 = r * r, r4 = r2 * r2, r8 = r4 * r4;
            float r3 = r2 * r, r5 = r4 * r, r6 = r4 * r2, r7 = r4 * r3;
            float pw[NS] = {r, r2, r3, r4, r5, r6, r7, r8,
                            r8 * r, r8 * r2, r8 * r3, r8 * r4,
                            r8 * r5, r8 * r6, r8 * r7, r8 * r8};
#pragma unroll
            for (int n = 0; n < NS; n++) h[n] = g_hc[dir][bb][j][n][d] + pw[n] * h[n];
        } else {
#pragma unroll
            for (int n = 0; n < NS; n++)
                h[n] = g_hc[dir][bb][j][n][d] + __expf(A[n] * S) * h[n];
        }
    }

    __shared__ float4 sBC[8][8];
    for (int t0 = 0; t0 < CHT; t0 += 8) {
        float dl[8], ul[8], zl[8], ql[8];
#pragma unroll
        for (int i = 0; i < 8; i++) {
            dl[i] = __bfloat162float(delta[(size_t)(t0 + i) * DI]);
            ul[i] = __bfloat162float(u[(size_t)(t0 + i) * DI]);
            int t = tb + t0 + i;
            int op = dir ? (Ll - 1 - t) : t;
            zl[i] = zb[(size_t)op * DI];
            ql[i] = __expf(dl[i] * A[0]);
        }
        __syncthreads();
        {
            int tt = threadIdx.x >> 3, j = threadIdx.x & 7;
            sBC[tt][j] = *(const float4*)(dbc + (size_t)(t0 + tt) * DBCW + DTR + j * 4);
        }
        __syncthreads();
#pragma unroll
        for (int i = 0; i < 8; i++) {
            float4 b0 = sBC[i][0], b1 = sBC[i][1], b2 = sBC[i][2], b3 = sBC[i][3];
            float4 c0 = sBC[i][4], c1 = sBC[i][5], c2 = sBC[i][6], c3 = sBC[i][7];
            float Bv[NS] = {b0.x, b0.y, b0.z, b0.w, b1.x, b1.y, b1.z, b1.w,
                            b2.x, b2.y, b2.z, b2.w, b3.x, b3.y, b3.z, b3.w};
            float Cv[NS] = {c0.x, c0.y, c0.z, c0.w, c1.x, c1.y, c1.z, c1.w,
                            c2.x, c2.y, c2.z, c2.w, c3.x, c3.y, c3.z, c3.w};
            float dt = dl[i];
            float du = dt * ul[i];
            float y = 0.f;
            if (fast) {
                float q = ql[i];
                float q2 = q * q, q4 = q2 * q2, q8 = q4 * q4;
                float q3 = q2 * q, q5 = q4 * q, q6 = q4 * q2, q7 = q4 * q3;
                float pw[NS] = {q, q2, q3, q4, q5, q6, q7, q8,
                                q8 * q, q8 * q2, q8 * q3, q8 * q4,
                                q8 * q5, q8 * q6, q8 * q7, q8 * q8};
#pragma unroll
                for (int n = 0; n < NS; n++) {
                    h[n] = h[n] * pw[n] + du * Bv[n];
                    y += h[n] * Cv[n];
                }
            } else {
#pragma unroll
                for (int n = 0; n < NS; n++) {
                    float dA = __expf(dt * A[n]);
                    h[n] = h[n] * dA + du * Bv[n];
                    y += h[n] * Cv[n];
                }
            }
            y += ul[i] * Dv;
            float z = zl[i];
            float sz = z * (1.f / (1.f + __expf(-z)));
            int t = tb + t0 + i;
            int op = dir ? (Ll - 1 - t) : t;
            yout[(size_t)op * DI] = __float2bfloat16(y * sz);
        }
    }
}

// ---------------- launch ----------------
extern "C" void kernel_launch(void* const* d_in, const int* in_sizes, int n_in,
                              void* d_out, int out_size) {
    const float* x        = (const float*)d_in[0];
    const float* ln_w     = (const float*)d_in[1];
    const float* ln_b     = (const float*)d_in[2];
    const float* in_proj  = (const float*)d_in[3];
    const float* out_proj = (const float*)d_in[4];
    const float* cw_f     = (const float*)d_in[5];
    const float* cb_f     = (const float*)d_in[6];
    const float* xw_f     = (const float*)d_in[7];
    const float* dtw_f    = (const float*)d_in[8];
    const float* dtb_f    = (const float*)d_in[9];
    const float* Alog_f   = (const float*)d_in[10];
    const float* Dv_f     = (const float*)d_in[11];
    const float* cw_b     = (const float*)d_in[12];
    const float* cb_b     = (const float*)d_in[13];
    const float* xw_b     = (const float*)d_in[14];
    const float* dtw_b    = (const float*)d_in[15];
    const float* dtb_b    = (const float*)d_in[16];
    const float* Alog_b   = (const float*)d_in[17];
    const float* Dv_b     = (const float*)d_in[18];
    float* out = (float*)d_out;

    ln_kernel<<<BLr / 8, 256>>>(x, ln_w, ln_b);
    transpose_all<<<(TIN + TOUT + TX + 255) / 256, 256>>>(in_proj, out_proj, xw_f, xw_b);
    mm_in_bf16<<<dim3(12, 128), 256>>>();
    conv_chunk_kernel<<<dim3(1, Bb * NCH, 2), 384>>>(cw_f, cb_f, cw_b, cb_b);
    mm_x_bf16<<<dim3(1, 128, 2), 256>>>();
    dtproj_kernel<<<dim3(3, BLr / 32, 2), 256>>>(dtw_f, dtb_f, dtw_b, dtb_b);
    scan_pass1<<<dim3(12, 128, 2), 64>>>(Alog_f, Alog_b);
    scan_pass3<<<dim3(12, 128, 2), 64>>>(Alog_f, Alog_b, Dv_f, Dv_b);
    mm_out_bf16<<<dim3(3, 128), 256>>>(x, out);
}